// round 14
// baseline (speedup 1.0000x reference)
#include <cuda_runtime.h>
#include <cuda_fp16.h>
#include <cstdint>

#define MAX_NODES 50000

__device__ float g_agg[MAX_NODES * 64];
__device__ float g_deg[MAX_NODES];
__device__ float g_P[MAX_NODES * 128];   // P[v] = feats[v] @ [W1e[0:64]||W1e[64:128]]

// ---------------- helpers ----------------
__device__ __forceinline__ void mma16816(float d[4], const uint32_t a[4],
                                         const uint32_t b[2]) {
    asm("mma.sync.aligned.m16n8k16.row.col.f32.f16.f16.f32 "
        "{%0,%1,%2,%3}, {%4,%5,%6,%7}, {%8,%9}, {%0,%1,%2,%3};"
        : "+f"(d[0]), "+f"(d[1]), "+f"(d[2]), "+f"(d[3])
        : "r"(a[0]), "r"(a[1]), "r"(a[2]), "r"(a[3]), "r"(b[0]), "r"(b[1]));
}

__device__ __forceinline__ void ldsm_x4(uint32_t r[4], uint32_t addr) {
    asm volatile("ldmatrix.sync.aligned.m8n8.x4.shared.b16 {%0,%1,%2,%3}, [%4];"
        : "=r"(r[0]), "=r"(r[1]), "=r"(r[2]), "=r"(r[3]) : "r"(addr));
}

__device__ __forceinline__ uint32_t packh2(float a, float b) {
    __half2 p = __floats2half2_rn(a, b);
    return *(uint32_t*)&p;
}

__device__ __forceinline__ void wsplit(float w, __half& hh, __half& hl) {
    hh = __float2half_rn(w);
    hl = __float2half_rn(w - __half2float(hh));
}

__device__ __forceinline__ void red_add2(float* addr, float a, float b) {
    asm volatile("red.global.add.v2.f32 [%0], {%1, %2};"
                 :: "l"(addr), "f"(a), "f"(b) : "memory");
}

__device__ __forceinline__ void prefetch_l1(const void* p) {
    asm volatile("prefetch.global.L1 [%0];" :: "l"(p));
}

// ---------------- kernel 0: zero scratch ----------------
__global__ void zero_kernel(int n_nodes) {
    int i = blockIdx.x * blockDim.x + threadIdx.x;
    int stride = gridDim.x * blockDim.x;
    int tot = n_nodes * 64;
    for (int k = i; k < tot; k += stride) g_agg[k] = 0.0f;
    for (int k = i; k < n_nodes; k += stride) g_deg[k] = 0.0f;
}

// ======================= P precompute kernel (+ deg counting) =======================
#define P_SA    0u
#define P_SW_HI 18432u
#define P_SW_LO 36864u
#define P_SMEM  55296u

__global__ void __launch_bounds__(256, 2) pnode_kernel(
    const float* __restrict__ feats,
    const float* __restrict__ W1e,
    const int* __restrict__ edge_index,
    int n_nodes, int n_edges)
{
    extern __shared__ char smem[];
    uint32_t* sA = (uint32_t*)(smem + P_SA);

    int tid = threadIdx.x;

    // ---- deg counting (moved off the edge kernel's critical path) ----
    for (int i = blockIdx.x * 256 + tid; i < n_edges; i += gridDim.x * 256) {
        int c = ((const int2*)edge_index)[i].y;
        atomicAdd(&g_deg[c], 1.0f);
    }

    for (int i = tid; i < 128 * 64; i += 256) {
        int n = i & 127, k = i >> 7;
        float w = (n < 64) ? W1e[k * 64 + n] : W1e[(64 + k) * 64 + (n - 64)];
        __half wh, wl;
        wsplit(w, wh, wl);
        ((__half*)(smem + P_SW_HI))[n * 72 + k] = wh;
        ((__half*)(smem + P_SW_LO))[n * 72 + k] = wl;
    }
    __syncthreads();

    const int warp = tid >> 5, lane = tid & 31;
    const int g = lane >> 2, t = lane & 3;
    const int wr = warp << 4;

    const int r8 = lane & 7;
    const int m01 = (lane >> 3) & 1;
    const int q01 = lane >> 4;
    uint32_t sbase = (uint32_t)__cvta_generic_to_shared(smem);
    uint32_t a0 = sbase + P_SA + ((uint32_t)(wr + r8 + m01 * 8) * 36u + q01 * 4u) * 4u;
    uint32_t bOff = ((uint32_t)(q01 * 8 + r8) * 36u + m01 * 4u) * 4u;

    int nTiles = (n_nodes + 127) >> 7;

    for (int tile = blockIdx.x; tile < nTiles; tile += gridDim.x) {
        int nbase = tile << 7;
        {
            size_t base4 = (size_t)(nbase + wr) * 16;
            size_t max4 = (size_t)n_nodes * 16 - 1;
            #pragma unroll
            for (int j = 0; j < 8; j++) {
                int idx = j * 32 + lane;
                size_t gidx = base4 + idx; if (gidx > max4) gidx = max4;
                float4 va = ((const float4*)feats)[gidx];
                int rloc = wr + (idx >> 4);
                int c4 = idx & 15;
                *(uint2*)(sA + rloc * 36 + c4 * 2) =
                    make_uint2(packh2(va.x, va.y), packh2(va.z, va.w));
            }
        }
        __syncwarp();

        float d[16][4];
        #pragma unroll
        for (int i = 0; i < 16; i++)
            #pragma unroll
            for (int j = 0; j < 4; j++) d[i][j] = 0.0f;

        #pragma unroll 1
        for (int kt = 0; kt < 4; kt++) {
            uint32_t ah[4];
            ldsm_x4(ah, a0 + kt * 32u);
            uint32_t wHi = sbase + P_SW_HI + bOff + kt * 32u;
            uint32_t wLo = sbase + P_SW_LO + bOff + kt * 32u;
            #pragma unroll
            for (int p = 0; p < 8; p++) {
                uint32_t bh[4], bl[4];
                ldsm_x4(bh, wHi + p * 2304u);
                ldsm_x4(bl, wLo + p * 2304u);
                mma16816(d[2 * p],     ah, bh);
                mma16816(d[2 * p + 1], ah, bh + 2);
                mma16816(d[2 * p],     ah, bl);
                mma16816(d[2 * p + 1], ah, bl + 2);
            }
        }

        {
            int r0 = nbase + wr + g, r1 = r0 + 8;
            bool v0 = r0 < n_nodes, v1 = r1 < n_nodes;
            #pragma unroll
            for (int nt = 0; nt < 16; nt++) {
                int c0 = nt * 8 + 2 * t;
                if (v0) *(float2*)(g_P + (size_t)r0 * 128 + c0) =
                            make_float2(d[nt][0], d[nt][1]);
                if (v1) *(float2*)(g_P + (size_t)r1 * 128 + c0) =
                            make_float2(d[nt][2], d[nt][3]);
            }
        }
        __syncwarp();
    }
}

// ======================= edge kernel =======================
#define E_SA      0u
#define E_SW1_HI  18432u
#define E_SW1_LO  27648u
#define E_SH      36864u
#define E_SW2_HI  55296u
#define E_SW2_LO  64512u
#define E_BIAS1   73728u
#define E_BIAS2   73984u
#define E_SR      74240u
#define E_SC      74752u
#define E_SMEM    75264u

__global__ void __launch_bounds__(256, 2) edge_kernel(
    const float* __restrict__ feats,
    const int* __restrict__ edge_index,
    const float* __restrict__ edge_attr,
    const float* __restrict__ W1e, const float* __restrict__ b1e,
    const float* __restrict__ W2e, const float* __restrict__ b2e,
    float* __restrict__ e_out,
    int n_edges)
{
    extern __shared__ char smem[];
    uint32_t* sA = (uint32_t*)(smem + E_SA);
    uint32_t* sH = (uint32_t*)(smem + E_SH);
    float* bias1 = (float*)(smem + E_BIAS1);
    float* bias2 = (float*)(smem + E_BIAS2);
    int*   sr    = (int*)(smem + E_SR);
    int*   sc    = (int*)(smem + E_SC);

    int tid = threadIdx.x;

    for (int i = tid; i < 64 * 64; i += 256) {
        int k = i >> 6, n = i & 63;
        float w = W1e[(128 + k) * 64 + n];
        __half wh, wl;
        wsplit(w, wh, wl);
        ((__half*)(smem + E_SW1_HI))[n * 72 + k] = wh;
        ((__half*)(smem + E_SW1_LO))[n * 72 + k] = wl;
    }
    for (int i = tid; i < 64 * 64; i += 256) {
        int k = i >> 6, n = i & 63;
        float w = W2e[i];
        __half wh, wl;
        wsplit(w, wh, wl);
        ((__half*)(smem + E_SW2_HI))[n * 72 + k] = wh;
        ((__half*)(smem + E_SW2_LO))[n * 72 + k] = wl;
    }
    if (tid < 64) {
        bias1[tid] = b1e[tid];
        bias2[tid] = b2e[tid];
    }
    __syncthreads();

    const int warp = tid >> 5, lane = tid & 31;
    const int g = lane >> 2, t = lane & 3;
    const int wr = warp << 4;
    const int row = tid >> 1, half = tid & 1;

    const int r8 = lane & 7;
    const int m01 = (lane >> 3) & 1;
    const int q01 = lane >> 4;
    uint32_t sbase = (uint32_t)__cvta_generic_to_shared(smem);
    uint32_t fragRow = ((uint32_t)(wr + r8 + m01 * 8) * 36u + q01 * 4u) * 4u;
    uint32_t a0 = sbase + E_SA + fragRow;
    uint32_t h0a = sbase + E_SH + fragRow;
    uint32_t bOff = ((uint32_t)(q01 * 8 + r8) * 36u + m01 * 4u) * 4u;

    int nTiles = (n_edges + 127) >> 7;

    for (int tile = blockIdx.x; tile < nTiles; tile += gridDim.x) {
        int ebase = tile << 7;

        // ---- indices ----
        {
            int er = ebase + row;
            int eid = er < n_edges ? er : (n_edges - 1);
            if (half == 0) {
                int2 rc = ((const int2*)edge_index)[eid];
                sr[row] = rc.x;
                sc[row] = rc.y;
            }
        }
        __syncwarp();

        // ---- prefetch this tile's P lines into L1 (2 instrs cover 64 lines/warp) ----
        {
            int e = lane & 15;
            int hl = (lane >> 4) * 32;
            prefetch_l1(g_P + (size_t)sr[wr + e] * 128 + hl);
            prefetch_l1(g_P + (size_t)sc[wr + e] * 128 + 64 + hl);
        }

        // ---- coalesced edge_attr gather ----
        {
            size_t base4 = (size_t)(ebase + wr) * 16;
            size_t max4 = (size_t)n_edges * 16 - 1;
            #pragma unroll
            for (int j = 0; j < 8; j++) {
                int idx = j * 32 + lane;
                size_t gidx = base4 + idx; if (gidx > max4) gidx = max4;
                float4 va = ((const float4*)edge_attr)[gidx];
                int rloc = wr + (idx >> 4);
                int c4 = idx & 15;
                *(uint2*)(sA + rloc * 36 + c4 * 2) =
                    make_uint2(packh2(va.x, va.y), packh2(va.z, va.w));
            }
        }
        __syncwarp();

        // ---- GEMM1: edge_attr @ W1c, K=64 (fp16 2-pass) ----
        float d[8][4];
        #pragma unroll
        for (int i = 0; i < 8; i++)
            #pragma unroll
            for (int j = 0; j < 4; j++) d[i][j] = 0.0f;

        #pragma unroll 1
        for (int kt = 0; kt < 4; kt++) {
            uint32_t ah[4];
            ldsm_x4(ah, a0 + kt * 32u);
            uint32_t wHi = sbase + E_SW1_HI + bOff + kt * 32u;
            uint32_t wLo = sbase + E_SW1_LO + bOff + kt * 32u;
            #pragma unroll
            for (int p = 0; p < 4; p++) {
                uint32_t bh[4], bl[4];
                ldsm_x4(bh, wHi + p * 2304u);
                ldsm_x4(bl, wLo + p * 2304u);
                mma16816(d[2 * p],     ah, bh);
                mma16816(d[2 * p + 1], ah, bh + 2);
                mma16816(d[2 * p],     ah, bl);
                mma16816(d[2 * p + 1], ah, bl + 2);
            }
        }

        // ---- epilogue 1: h = relu(d + P[r][c] + P[c][64+c] + b1) -> sH (hi only) ----
        {
            int rr0 = sr[wr + g],     cc0 = sc[wr + g];
            int rr1 = sr[wr + 8 + g], cc1 = sc[wr + 8 + g];
            const float* P0r = g_P + (size_t)rr0 * 128;
            const float* P0c = g_P + (size_t)cc0 * 128 + 64;
            const float* P1r = g_P + (size_t)rr1 * 128;
            const float* P1c = g_P + (size_t)cc1 * 128 + 64;
            #pragma unroll
            for (int nt = 0; nt < 8; nt++) {
                int c0 = nt * 8 + 2 * t;
                float2 pa = *(const float2*)(P0r + c0);
                float2 pb = *(const float2*)(P0c + c0);
                float2 pc_ = *(const float2*)(P1r + c0);
                float2 pd = *(const float2*)(P1c + c0);
                float bb0 = bias1[c0], bb1 = bias1[c0 + 1];
                float h0 = fmaxf(d[nt][0] + pa.x + pb.x + bb0, 0.f);
                float h1 = fmaxf(d[nt][1] + pa.y + pb.y + bb1, 0.f);
                float h2 = fmaxf(d[nt][2] + pc_.x + pd.x + bb0, 0.f);
                float h3 = fmaxf(d[nt][3] + pc_.y + pd.y + bb1, 0.f);
                int w0 = (wr + g) * 36 + nt * 4 + t;
                sH[w0]       = packh2(h0, h1);
                sH[w0 + 288] = packh2(h2, h3);
            }
        }
        __syncwarp();

        // ---- GEMM2: K=64 (fp16 2-pass) ----
        float d2[8][4];
        #pragma unroll
        for (int i = 0; i < 8; i++)
            #pragma unroll
            for (int j = 0; j < 4; j++) d2[i][j] = 0.0f;

        #pragma unroll 1
        for (int kt = 0; kt < 4; kt++) {
            uint32_t ah[4];
            ldsm_x4(ah, h0a + kt * 32u);
            uint32_t wHi = sbase + E_SW2_HI + bOff + kt * 32u;
            uint32_t wLo = sbase + E_SW2_LO + bOff + kt * 32u;
            #pragma unroll
            for (int p = 0; p < 4; p++) {
                uint32_t bh[4], bl[4];
                ldsm_x4(bh, wHi + p * 2304u);
                ldsm_x4(bl, wLo + p * 2304u);
                mma16816(d2[2 * p],     ah, bh);
                mma16816(d2[2 * p + 1], ah, bh + 2);
                mma16816(d2[2 * p],     ah, bl);
                mma16816(d2[2 * p + 1], ah, bl + 2);
            }
        }

        // ---- epilogue 2: e = D2 + b2 -> e_out + vector red to g_agg ----
        {
            int r0 = ebase + wr + g, r1 = r0 + 8;
            bool v0 = r0 < n_edges, v1 = r1 < n_edges;
            int ca = sc[wr + g], cb = sc[wr + 8 + g];
            #pragma unroll
            for (int nt = 0; nt < 8; nt++) {
                int c0 = nt * 8 + 2 * t;
                float bb0 = bias2[c0], bb1 = bias2[c0 + 1];
                float e0 = d2[nt][0] + bb0, e1 = d2[nt][1] + bb1;
                float e2 = d2[nt][2] + bb0, e3 = d2[nt][3] + bb1;
                if (v0) {
                    *(float2*)(e_out + (size_t)r0 * 64 + c0) = make_float2(e0, e1);
                    red_add2(g_agg + (size_t)ca * 64 + c0, e0, e1);
                }
                if (v1) {
                    *(float2*)(e_out + (size_t)r1 * 64 + c0) = make_float2(e2, e3);
                    red_add2(g_agg + (size_t)cb * 64 + c0, e2, e3);
                }
            }
        }
        __syncwarp();
    }
}

// ======================= node kernel =======================
#define N_SA      0u
#define N_SW1_HI  34816u
#define N_SW1_LO  52224u
#define N_SH      69632u
#define N_SW2_HI  88064u
#define N_SW2_LO  97280u
#define N_BIAS1   106496u
#define N_BIAS2   106752u
#define N_SMEM    107008u

__global__ void __launch_bounds__(256, 1) node_kernel(
    const float* __restrict__ feats,
    const float* __restrict__ W1n, const float* __restrict__ b1n,
    const float* __restrict__ W2n, const float* __restrict__ b2n,
    float* __restrict__ feats_out,
    int n_nodes)
{
    extern __shared__ char smem[];
    uint32_t* sA = (uint32_t*)(smem + N_SA);
    uint32_t* sH = (uint32_t*)(smem + N_SH);
    float* bias1 = (float*)(smem + N_BIAS1);
    float* bias2 = (float*)(smem + N_BIAS2);

    int tid = threadIdx.x;

    for (int i = tid; i < 128 * 64; i += 256) {
        int k = i >> 6, n = i & 63;
        float w = W1n[i];
        __half wh, wl;
        wsplit(w, wh, wl);
        ((__half*)(smem + N_SW1_HI))[n * 136 + k] = wh;
        ((__half*)(smem + N_SW1_LO))[n * 136 + k] = wl;
    }
    for (int i = tid; i < 64 * 64; i += 256) {
        int k = i >> 6, n = i & 63;
        float w = W2n[i];
        __half wh, wl;
        wsplit(w, wh, wl);
        ((__half*)(smem + N_SW2_HI))[n * 72 + k] = wh;
        ((__half*)(smem + N_SW2_LO))[n * 72 + k] = wl;
    }
    if (tid < 64) {
        bias1[tid] = b1n[tid];
        bias2[tid] = b2n[tid];
    }
    __syncthreads();

    const int warp = tid >> 5, lane = tid & 31;
    const int g = lane >> 2, t = lane & 3;
    const int wr = warp << 4;

    const int r8 = lane & 7;
    const int m01 = (lane >> 3) & 1;
    const int q01 = lane >> 4;
    uint32_t sbase = (uint32_t)__cvta_generic_to_shared(smem);
    uint32_t a0 = sbase + N_SA + ((uint32_t)(wr + r8 + m01 * 8) * 68u + q01 * 4u) * 4u;
    uint32_t fragRow36 = ((uint32_t)(wr + r8 + m01 * 8) * 36u + q01 * 4u) * 4u;
    uint32_t h0a = sbase + N_SH + fragRow36;
    uint32_t bOff68 = ((uint32_t)(q01 * 8 + r8) * 68u + m01 * 4u) * 4u;
    uint32_t bOff36 = ((uint32_t)(q01 * 8 + r8) * 36u + m01 * 4u) * 4u;

    int nTiles = (n_nodes + 127) >> 7;

    for (int tile = blockIdx.x; tile < nTiles; tile += gridDim.x) {
        int nbase = tile << 7;

        {
            float invdReg;
            {
                int r16 = nbase + wr + (lane & 15);
                int nid = r16 < n_nodes ? r16 : (n_nodes - 1);
                invdReg = 1.0f / fmaxf(g_deg[nid], 1.0f);
            }
            size_t base4 = (size_t)(nbase + wr) * 16;
            size_t max4 = (size_t)n_nodes * 16 - 1;
            #pragma unroll
            for (int j = 0; j < 8; j++) {
                int idx = j * 32 + lane;
                size_t gidx = base4 + idx; if (gidx > max4) gidx = max4;
                float4 va = ((const float4*)feats)[gidx];
                int rloc = wr + (idx >> 4);
                int c4 = idx & 15;
                *(uint2*)(sA + rloc * 68 + c4 * 2) =
                    make_uint2(packh2(va.x, va.y), packh2(va.z, va.w));
            }
            #pragma unroll
            for (int j = 0; j < 8; j++) {
                int idx = j * 32 + lane;
                size_t gidx = base4 + idx; if (gidx > max4) gidx = max4;
                float4 va = ((const float4*)g_agg)[gidx];
                float s = __shfl_sync(0xffffffffu, invdReg, idx >> 4);
                va.x *= s; va.y *= s; va.z *= s; va.w *= s;
                int rloc = wr + (idx >> 4);
                int c4 = idx & 15;
                *(uint2*)(sA + rloc * 68 + 32 + c4 * 2) =
                    make_uint2(packh2(va.x, va.y), packh2(va.z, va.w));
            }
        }
        __syncwarp();

        float d[8][4];
        #pragma unroll
        for (int i = 0; i < 8; i++)
            #pragma unroll
            for (int j = 0; j < 4; j++) d[i][j] = 0.0f;

        #pragma unroll 1
        for (int kt = 0; kt < 8; kt++) {
            uint32_t ah[4];
            ldsm_x4(ah, a0 + kt * 32u);
            uint32_t wHi = sbase + N_SW1_HI + bOff68 + kt * 32u;
            uint32_t wLo = sbase + N_SW1_LO + bOff68 + kt * 32u;
            #pragma unroll
            for (int p = 0; p < 4; p++) {
                uint32_t bh[4], bl[4];
                ldsm_x4(bh, wHi + p * 4352u);
                ldsm_x4(bl, wLo + p * 4352u);
                mma16816(d[2 * p],     ah, bh);
                mma16816(d[2 * p + 1], ah, bh + 2);
                mma16816(d[2 * p],     ah, bl);
                mma16816(d[2 * p + 1], ah, bl + 2);
            }
        }

        #pragma unroll
        for (int nt = 0; nt < 8; nt++) {
            int c0 = nt * 8 + 2 * t;
            float bb0 = bias1[c0], bb1 = bias1[c0 + 1];
            float h0 = fmaxf(d[nt][0] + bb0, 0.f), h1 = fmaxf(d[nt][1] + bb1, 0.f);
            float h2 = fmaxf(d[nt][2] + bb0, 0.f), h3 = fmaxf(d[nt][3] + bb1, 0.f);
            int w0 = (wr + g) * 36 + nt * 4 + t;
            sH[w0]       = packh2(h0, h1);
            sH[w0 + 288] = packh2(h2, h3);
        }
        __syncwarp();

        float d2[8][4];
        #pragma unroll
        for (int i = 0; i < 8; i++)
            #pragma unroll
            for (int j = 0; j < 4; j++) d2[i][j] = 0.0f;

        #pragma unroll 1
        for (int kt = 0; kt < 4; kt++) {
            uint32_t ah[4];
            ldsm_x4(ah, h0a + kt * 32u);
            uint32_t wHi = sbase + N_SW2_HI + bOff36 + kt * 32u;
            uint32_t wLo = sbase + N_SW2_LO + bOff36 + kt * 32u;
            #pragma unroll
            for (int p = 0; p < 4; p++) {
                uint32_t bh[4], bl[4];
                ldsm_x4(bh, wHi + p * 2304u);
                ldsm_x4(bl, wLo + p * 2304u);
                mma16816(d2[2 * p],     ah, bh);
                mma16816(d2[2 * p + 1], ah, bh + 2);
                mma16816(d2[2 * p],     ah, bl);
                mma16816(d2[2 * p + 1], ah, bl + 2);
            }
        }

        {
            int r0 = nbase + wr + g, r1 = r0 + 8;
            bool v0 = r0 < n_nodes, v1 = r1 < n_nodes;
            #pragma unroll
            for (int nt = 0; nt < 8; nt++) {
                int c0 = nt * 8 + 2 * t;
                float bb0 = bias2[c0], bb1 = bias2[c0 + 1];
                if (v0)
                    *(float2*)(feats_out + (size_t)r0 * 64 + c0) =
                        make_float2(d2[nt][0] + bb0, d2[nt][1] + bb1);
                if (v1)
                    *(float2*)(feats_out + (size_t)r1 * 64 + c0) =
                        make_float2(d2[nt][2] + bb0, d2[nt][3] + bb1);
            }
        }
        __syncwarp();
    }
}

// ======================= launch =======================
extern "C" void kernel_launch(void* const* d_in, const int* in_sizes, int n_in,
                              void* d_out, int out_size) {
    const float* feats      = (const float*)d_in[0];
    const int*   edge_index = (const int*)d_in[1];
    const float* edge_attr  = (const float*)d_in[2];
    const float* W1e        = (const float*)d_in[3];
    const float* b1e        = (const float*)d_in[4];
    const float* W2e        = (const float*)d_in[5];
    const float* b2e        = (const float*)d_in[6];
    const float* W1n        = (const float*)d_in[7];
    const float* b1n        = (const float*)d_in[8];
    const float* W2n        = (const float*)d_in[9];
    const float* b2n        = (const float*)d_in[10];

    int n_nodes = in_sizes[0] / 64;
    int n_edges = in_sizes[2] / 64;

    float* out       = (float*)d_out;
    float* feats_out = out;                          // [n_nodes, 64]
    float* e_out     = out + (size_t)n_nodes * 64;   // [n_edges, 64]

    cudaFuncSetAttribute(pnode_kernel, cudaFuncAttributeMaxDynamicSharedMemorySize, P_SMEM);
    cudaFuncSetAttribute(edge_kernel, cudaFuncAttributeMaxDynamicSharedMemorySize, E_SMEM);
    cudaFuncSetAttribute(node_kernel, cudaFuncAttributeMaxDynamicSharedMemorySize, N_SMEM);

    zero_kernel<<<1024, 256>>>(n_nodes);
    pnode_kernel<<<296, 256, P_SMEM>>>(feats, W1e, edge_index, n_nodes, n_edges);
    edge_kernel<<<296, 256, E_SMEM>>>(feats, edge_index, edge_attr,
                                      W1e, b1e, W2e, b2e, e_out, n_edges);
    node_kernel<<<148, 256, N_SMEM>>>(feats, W1n, b1n, W2n, b2n,
                                      feats_out, n_nodes);
}

// round 15
// speedup vs baseline: 1.0226x; 1.0226x over previous
#include <cuda_runtime.h>
#include <cuda_fp16.h>
#include <cstdint>

#define MAX_NODES 50000

__device__ float g_agg[MAX_NODES * 64];
__device__ float g_deg[MAX_NODES];
__device__ float g_P[MAX_NODES * 128];   // P[v] = feats[v] @ [W1e[0:64]||W1e[64:128]]

// ---------------- helpers ----------------
__device__ __forceinline__ void mma16816(float d[4], const uint32_t a[4],
                                         const uint32_t b[2]) {
    asm("mma.sync.aligned.m16n8k16.row.col.f32.f16.f16.f32 "
        "{%0,%1,%2,%3}, {%4,%5,%6,%7}, {%8,%9}, {%0,%1,%2,%3};"
        : "+f"(d[0]), "+f"(d[1]), "+f"(d[2]), "+f"(d[3])
        : "r"(a[0]), "r"(a[1]), "r"(a[2]), "r"(a[3]), "r"(b[0]), "r"(b[1]));
}

__device__ __forceinline__ void ldsm_x4(uint32_t r[4], uint32_t addr) {
    asm volatile("ldmatrix.sync.aligned.m8n8.x4.shared.b16 {%0,%1,%2,%3}, [%4];"
        : "=r"(r[0]), "=r"(r[1]), "=r"(r[2]), "=r"(r[3]) : "r"(addr));
}

__device__ __forceinline__ uint32_t packh2(float a, float b) {
    __half2 p = __floats2half2_rn(a, b);
    return *(uint32_t*)&p;
}

__device__ __forceinline__ void wsplit(float w, __half& hh, __half& hl) {
    hh = __float2half_rn(w);
    hl = __float2half_rn(w - __half2float(hh));
}

__device__ __forceinline__ void red_add2(float* addr, float a, float b) {
    asm volatile("red.global.add.v2.f32 [%0], {%1, %2};"
                 :: "l"(addr), "f"(a), "f"(b) : "memory");
}

// streaming (evict-first) load/store: keep L2 for g_P / g_agg
__device__ __forceinline__ float4 ldg_cs4(const float4* p) {
    float4 v;
    asm volatile("ld.global.cs.v4.f32 {%0,%1,%2,%3}, [%4];"
        : "=f"(v.x), "=f"(v.y), "=f"(v.z), "=f"(v.w) : "l"(p));
    return v;
}
__device__ __forceinline__ void stg_cs2(float* p, float a, float b) {
    asm volatile("st.global.cs.v2.f32 [%0], {%1, %2};"
        :: "l"(p), "f"(a), "f"(b) : "memory");
}

// ---------------- kernel 0: zero scratch ----------------
__global__ void zero_kernel(int n_nodes) {
    int i = blockIdx.x * blockDim.x + threadIdx.x;
    int stride = gridDim.x * blockDim.x;
    int tot = n_nodes * 64;
    for (int k = i; k < tot; k += stride) g_agg[k] = 0.0f;
    for (int k = i; k < n_nodes; k += stride) g_deg[k] = 0.0f;
}

// ======================= P precompute kernel =======================
#define P_SA    0u
#define P_SW_HI 18432u
#define P_SW_LO 36864u
#define P_SMEM  55296u

__global__ void __launch_bounds__(256, 2) pnode_kernel(
    const float* __restrict__ feats,
    const float* __restrict__ W1e,
    int n_nodes)
{
    extern __shared__ char smem[];
    uint32_t* sA = (uint32_t*)(smem + P_SA);

    int tid = threadIdx.x;
    for (int i = tid; i < 128 * 64; i += 256) {
        int n = i & 127, k = i >> 7;
        float w = (n < 64) ? W1e[k * 64 + n] : W1e[(64 + k) * 64 + (n - 64)];
        __half wh, wl;
        wsplit(w, wh, wl);
        ((__half*)(smem + P_SW_HI))[n * 72 + k] = wh;
        ((__half*)(smem + P_SW_LO))[n * 72 + k] = wl;
    }
    __syncthreads();

    const int warp = tid >> 5, lane = tid & 31;
    const int g = lane >> 2, t = lane & 3;
    const int wr = warp << 4;

    const int r8 = lane & 7;
    const int m01 = (lane >> 3) & 1;
    const int q01 = lane >> 4;
    uint32_t sbase = (uint32_t)__cvta_generic_to_shared(smem);
    uint32_t a0 = sbase + P_SA + ((uint32_t)(wr + r8 + m01 * 8) * 36u + q01 * 4u) * 4u;
    uint32_t bOff = ((uint32_t)(q01 * 8 + r8) * 36u + m01 * 4u) * 4u;

    int nTiles = (n_nodes + 127) >> 7;

    for (int tile = blockIdx.x; tile < nTiles; tile += gridDim.x) {
        int nbase = tile << 7;
        {
            size_t base4 = (size_t)(nbase + wr) * 16;
            size_t max4 = (size_t)n_nodes * 16 - 1;
            #pragma unroll
            for (int j = 0; j < 8; j++) {
                int idx = j * 32 + lane;
                size_t gidx = base4 + idx; if (gidx > max4) gidx = max4;
                float4 va = ((const float4*)feats)[gidx];
                int rloc = wr + (idx >> 4);
                int c4 = idx & 15;
                *(uint2*)(sA + rloc * 36 + c4 * 2) =
                    make_uint2(packh2(va.x, va.y), packh2(va.z, va.w));
            }
        }
        __syncwarp();

        float d[16][4];
        #pragma unroll
        for (int i = 0; i < 16; i++)
            #pragma unroll
            for (int j = 0; j < 4; j++) d[i][j] = 0.0f;

        #pragma unroll 1
        for (int kt = 0; kt < 4; kt++) {
            uint32_t ah[4];
            ldsm_x4(ah, a0 + kt * 32u);
            uint32_t wHi = sbase + P_SW_HI + bOff + kt * 32u;
            uint32_t wLo = sbase + P_SW_LO + bOff + kt * 32u;
            #pragma unroll
            for (int p = 0; p < 8; p++) {
                uint32_t bh[4], bl[4];
                ldsm_x4(bh, wHi + p * 2304u);
                ldsm_x4(bl, wLo + p * 2304u);
                mma16816(d[2 * p],     ah, bh);
                mma16816(d[2 * p + 1], ah, bh + 2);
                mma16816(d[2 * p],     ah, bl);
                mma16816(d[2 * p + 1], ah, bl + 2);
            }
        }

        {
            int r0 = nbase + wr + g, r1 = r0 + 8;
            bool v0 = r0 < n_nodes, v1 = r1 < n_nodes;
            #pragma unroll
            for (int nt = 0; nt < 16; nt++) {
                int c0 = nt * 8 + 2 * t;
                if (v0) *(float2*)(g_P + (size_t)r0 * 128 + c0) =
                            make_float2(d[nt][0], d[nt][1]);
                if (v1) *(float2*)(g_P + (size_t)r1 * 128 + c0) =
                            make_float2(d[nt][2], d[nt][3]);
            }
        }
        __syncwarp();
    }
}

// ======================= edge kernel =======================
#define E_SA      0u
#define E_SW1_HI  18432u
#define E_SW1_LO  27648u
#define E_SH      36864u
#define E_SW2_HI  55296u
#define E_SW2_LO  64512u
#define E_BIAS1   73728u
#define E_BIAS2   73984u
#define E_SR      74240u
#define E_SC      74752u
#define E_SMEM    75264u

__global__ void __launch_bounds__(256, 2) edge_kernel(
    const float* __restrict__ feats,
    const int* __restrict__ edge_index,
    const float* __restrict__ edge_attr,
    const float* __restrict__ W1e, const float* __restrict__ b1e,
    const float* __restrict__ W2e, const float* __restrict__ b2e,
    float* __restrict__ e_out,
    int n_edges)
{
    extern __shared__ char smem[];
    uint32_t* sA = (uint32_t*)(smem + E_SA);
    uint32_t* sH = (uint32_t*)(smem + E_SH);
    float* bias1 = (float*)(smem + E_BIAS1);
    float* bias2 = (float*)(smem + E_BIAS2);
    int*   sr    = (int*)(smem + E_SR);
    int*   sc    = (int*)(smem + E_SC);

    int tid = threadIdx.x;

    for (int i = tid; i < 64 * 64; i += 256) {
        int k = i >> 6, n = i & 63;
        float w = W1e[(128 + k) * 64 + n];
        __half wh, wl;
        wsplit(w, wh, wl);
        ((__half*)(smem + E_SW1_HI))[n * 72 + k] = wh;
        ((__half*)(smem + E_SW1_LO))[n * 72 + k] = wl;
    }
    for (int i = tid; i < 64 * 64; i += 256) {
        int k = i >> 6, n = i & 63;
        float w = W2e[i];
        __half wh, wl;
        wsplit(w, wh, wl);
        ((__half*)(smem + E_SW2_HI))[n * 72 + k] = wh;
        ((__half*)(smem + E_SW2_LO))[n * 72 + k] = wl;
    }
    if (tid < 64) {
        bias1[tid] = b1e[tid];
        bias2[tid] = b2e[tid];
    }
    __syncthreads();

    const int warp = tid >> 5, lane = tid & 31;
    const int g = lane >> 2, t = lane & 3;
    const int wr = warp << 4;
    const int row = tid >> 1, half = tid & 1;

    const int r8 = lane & 7;
    const int m01 = (lane >> 3) & 1;
    const int q01 = lane >> 4;
    uint32_t sbase = (uint32_t)__cvta_generic_to_shared(smem);
    uint32_t fragRow = ((uint32_t)(wr + r8 + m01 * 8) * 36u + q01 * 4u) * 4u;
    uint32_t a0 = sbase + E_SA + fragRow;
    uint32_t h0a = sbase + E_SH + fragRow;
    uint32_t bOff = ((uint32_t)(q01 * 8 + r8) * 36u + m01 * 4u) * 4u;

    int nTiles = (n_edges + 127) >> 7;

    for (int tile = blockIdx.x; tile < nTiles; tile += gridDim.x) {
        int ebase = tile << 7;

        // ---- indices + deg ----
        {
            int er = ebase + row;
            bool v = er < n_edges;
            int eid = v ? er : (n_edges - 1);
            if (half == 0) {
                int2 rc = ((const int2*)edge_index)[eid];
                sr[row] = rc.x;
                sc[row] = rc.y;
                if (v) atomicAdd(&g_deg[rc.y], 1.0f);
            }
        }
        // ---- coalesced edge_attr gather (streaming loads) ----
        {
            size_t base4 = (size_t)(ebase + wr) * 16;
            size_t max4 = (size_t)n_edges * 16 - 1;
            #pragma unroll
            for (int j = 0; j < 8; j++) {
                int idx = j * 32 + lane;
                size_t gidx = base4 + idx; if (gidx > max4) gidx = max4;
                float4 va = ldg_cs4((const float4*)edge_attr + gidx);
                int rloc = wr + (idx >> 4);
                int c4 = idx & 15;
                *(uint2*)(sA + rloc * 36 + c4 * 2) =
                    make_uint2(packh2(va.x, va.y), packh2(va.z, va.w));
            }
        }
        __syncwarp();

        // ---- GEMM1: edge_attr @ W1c, K=64 (fp16 2-pass) ----
        float d[8][4];
        #pragma unroll
        for (int i = 0; i < 8; i++)
            #pragma unroll
            for (int j = 0; j < 4; j++) d[i][j] = 0.0f;

        #pragma unroll 1
        for (int kt = 0; kt < 4; kt++) {
            uint32_t ah[4];
            ldsm_x4(ah, a0 + kt * 32u);
            uint32_t wHi = sbase + E_SW1_HI + bOff + kt * 32u;
            uint32_t wLo = sbase + E_SW1_LO + bOff + kt * 32u;
            #pragma unroll
            for (int p = 0; p < 4; p++) {
                uint32_t bh[4], bl[4];
                ldsm_x4(bh, wHi + p * 2304u);
                ldsm_x4(bl, wLo + p * 2304u);
                mma16816(d[2 * p],     ah, bh);
                mma16816(d[2 * p + 1], ah, bh + 2);
                mma16816(d[2 * p],     ah, bl);
                mma16816(d[2 * p + 1], ah, bl + 2);
            }
        }

        // ---- epilogue 1: h = relu(d + P[r][c] + P[c][64+c] + b1) -> sH (hi only) ----
        {
            int rr0 = sr[wr + g],     cc0 = sc[wr + g];
            int rr1 = sr[wr + 8 + g], cc1 = sc[wr + 8 + g];
            const float* P0r = g_P + (size_t)rr0 * 128;
            const float* P0c = g_P + (size_t)cc0 * 128 + 64;
            const float* P1r = g_P + (size_t)rr1 * 128;
            const float* P1c = g_P + (size_t)cc1 * 128 + 64;
            #pragma unroll
            for (int nt = 0; nt < 8; nt++) {
                int c0 = nt * 8 + 2 * t;
                float2 pa = *(const float2*)(P0r + c0);
                float2 pb = *(const float2*)(P0c + c0);
                float2 pc_ = *(const float2*)(P1r + c0);
                float2 pd = *(const float2*)(P1c + c0);
                float bb0 = bias1[c0], bb1 = bias1[c0 + 1];
                float h0 = fmaxf(d[nt][0] + pa.x + pb.x + bb0, 0.f);
                float h1 = fmaxf(d[nt][1] + pa.y + pb.y + bb1, 0.f);
                float h2 = fmaxf(d[nt][2] + pc_.x + pd.x + bb0, 0.f);
                float h3 = fmaxf(d[nt][3] + pc_.y + pd.y + bb1, 0.f);
                int w0 = (wr + g) * 36 + nt * 4 + t;
                sH[w0]       = packh2(h0, h1);
                sH[w0 + 288] = packh2(h2, h3);
            }
        }
        __syncwarp();

        // ---- GEMM2: K=64 (fp16 2-pass) ----
        float d2[8][4];
        #pragma unroll
        for (int i = 0; i < 8; i++)
            #pragma unroll
            for (int j = 0; j < 4; j++) d2[i][j] = 0.0f;

        #pragma unroll 1
        for (int kt = 0; kt < 4; kt++) {
            uint32_t ah[4];
            ldsm_x4(ah, h0a + kt * 32u);
            uint32_t wHi = sbase + E_SW2_HI + bOff + kt * 32u;
            uint32_t wLo = sbase + E_SW2_LO + bOff + kt * 32u;
            #pragma unroll
            for (int p = 0; p < 4; p++) {
                uint32_t bh[4], bl[4];
                ldsm_x4(bh, wHi + p * 2304u);
                ldsm_x4(bl, wLo + p * 2304u);
                mma16816(d2[2 * p],     ah, bh);
                mma16816(d2[2 * p + 1], ah, bh + 2);
                mma16816(d2[2 * p],     ah, bl);
                mma16816(d2[2 * p + 1], ah, bl + 2);
            }
        }

        // ---- epilogue 2: e = D2 + b2 -> e_out (streaming) + red to g_agg ----
        {
            int r0 = ebase + wr + g, r1 = r0 + 8;
            bool v0 = r0 < n_edges, v1 = r1 < n_edges;
            int ca = sc[wr + g], cb = sc[wr + 8 + g];
            #pragma unroll
            for (int nt = 0; nt < 8; nt++) {
                int c0 = nt * 8 + 2 * t;
                float bb0 = bias2[c0], bb1 = bias2[c0 + 1];
                float e0 = d2[nt][0] + bb0, e1 = d2[nt][1] + bb1;
                float e2 = d2[nt][2] + bb0, e3 = d2[nt][3] + bb1;
                if (v0) {
                    stg_cs2(e_out + (size_t)r0 * 64 + c0, e0, e1);
                    red_add2(g_agg + (size_t)ca * 64 + c0, e0, e1);
                }
                if (v1) {
                    stg_cs2(e_out + (size_t)r1 * 64 + c0, e2, e3);
                    red_add2(g_agg + (size_t)cb * 64 + c0, e2, e3);
                }
            }
        }
        __syncwarp();
    }
}

// ======================= node kernel =======================
#define N_SA      0u
#define N_SW1_HI  34816u
#define N_SW1_LO  52224u
#define N_SH      69632u
#define N_SW2_HI  88064u
#define N_SW2_LO  97280u
#define N_BIAS1   106496u
#define N_BIAS2   106752u
#define N_SMEM    107008u

__global__ void __launch_bounds__(256, 1) node_kernel(
    const float* __restrict__ feats,
    const float* __restrict__ W1n, const float* __restrict__ b1n,
    const float* __restrict__ W2n, const float* __restrict__ b2n,
    float* __restrict__ feats_out,
    int n_nodes)
{
    extern __shared__ char smem[];
    uint32_t* sA = (uint32_t*)(smem + N_SA);
    uint32_t* sH = (uint32_t*)(smem + N_SH);
    float* bias1 = (float*)(smem + N_BIAS1);
    float* bias2 = (float*)(smem + N_BIAS2);

    int tid = threadIdx.x;

    for (int i = tid; i < 128 * 64; i += 256) {
        int k = i >> 6, n = i & 63;
        float w = W1n[i];
        __half wh, wl;
        wsplit(w, wh, wl);
        ((__half*)(smem + N_SW1_HI))[n * 136 + k] = wh;
        ((__half*)(smem + N_SW1_LO))[n * 136 + k] = wl;
    }
    for (int i = tid; i < 64 * 64; i += 256) {
        int k = i >> 6, n = i & 63;
        float w = W2n[i];
        __half wh, wl;
        wsplit(w, wh, wl);
        ((__half*)(smem + N_SW2_HI))[n * 72 + k] = wh;
        ((__half*)(smem + N_SW2_LO))[n * 72 + k] = wl;
    }
    if (tid < 64) {
        bias1[tid] = b1n[tid];
        bias2[tid] = b2n[tid];
    }
    __syncthreads();

    const int warp = tid >> 5, lane = tid & 31;
    const int g = lane >> 2, t = lane & 3;
    const int wr = warp << 4;

    const int r8 = lane & 7;
    const int m01 = (lane >> 3) & 1;
    const int q01 = lane >> 4;
    uint32_t sbase = (uint32_t)__cvta_generic_to_shared(smem);
    uint32_t a0 = sbase + N_SA + ((uint32_t)(wr + r8 + m01 * 8) * 68u + q01 * 4u) * 4u;
    uint32_t fragRow36 = ((uint32_t)(wr + r8 + m01 * 8) * 36u + q01 * 4u) * 4u;
    uint32_t h0a = sbase + N_SH + fragRow36;
    uint32_t bOff68 = ((uint32_t)(q01 * 8 + r8) * 68u + m01 * 4u) * 4u;
    uint32_t bOff36 = ((uint32_t)(q01 * 8 + r8) * 36u + m01 * 4u) * 4u;

    int nTiles = (n_nodes + 127) >> 7;

    for (int tile = blockIdx.x; tile < nTiles; tile += gridDim.x) {
        int nbase = tile << 7;

        {
            float invdReg;
            {
                int r16 = nbase + wr + (lane & 15);
                int nid = r16 < n_nodes ? r16 : (n_nodes - 1);
                invdReg = 1.0f / fmaxf(g_deg[nid], 1.0f);
            }
            size_t base4 = (size_t)(nbase + wr) * 16;
            size_t max4 = (size_t)n_nodes * 16 - 1;
            #pragma unroll
            for (int j = 0; j < 8; j++) {
                int idx = j * 32 + lane;
                size_t gidx = base4 + idx; if (gidx > max4) gidx = max4;
                float4 va = ((const float4*)feats)[gidx];
                int rloc = wr + (idx >> 4);
                int c4 = idx & 15;
                *(uint2*)(sA + rloc * 68 + c4 * 2) =
                    make_uint2(packh2(va.x, va.y), packh2(va.z, va.w));
            }
            #pragma unroll
            for (int j = 0; j < 8; j++) {
                int idx = j * 32 + lane;
                size_t gidx = base4 + idx; if (gidx > max4) gidx = max4;
                float4 va = ((const float4*)g_agg)[gidx];
                float s = __shfl_sync(0xffffffffu, invdReg, idx >> 4);
                va.x *= s; va.y *= s; va.z *= s; va.w *= s;
                int rloc = wr + (idx >> 4);
                int c4 = idx & 15;
                *(uint2*)(sA + rloc * 68 + 32 + c4 * 2) =
                    make_uint2(packh2(va.x, va.y), packh2(va.z, va.w));
            }
        }
        __syncwarp();

        float d[8][4];
        #pragma unroll
        for (int i = 0; i < 8; i++)
            #pragma unroll
            for (int j = 0; j < 4; j++) d[i][j] = 0.0f;

        #pragma unroll 1
        for (int kt = 0; kt < 8; kt++) {
            uint32_t ah[4];
            ldsm_x4(ah, a0 + kt * 32u);
            uint32_t wHi = sbase + N_SW1_HI + bOff68 + kt * 32u;
            uint32_t wLo = sbase + N_SW1_LO + bOff68 + kt * 32u;
            #pragma unroll
            for (int p = 0; p < 4; p++) {
                uint32_t bh[4], bl[4];
                ldsm_x4(bh, wHi + p * 4352u);
                ldsm_x4(bl, wLo + p * 4352u);
                mma16816(d[2 * p],     ah, bh);
                mma16816(d[2 * p + 1], ah, bh + 2);
                mma16816(d[2 * p],     ah, bl);
                mma16816(d[2 * p + 1], ah, bl + 2);
            }
        }

        #pragma unroll
        for (int nt = 0; nt < 8; nt++) {
            int c0 = nt * 8 + 2 * t;
            float bb0 = bias1[c0], bb1 = bias1[c0 + 1];
            float h0 = fmaxf(d[nt][0] + bb0, 0.f), h1 = fmaxf(d[nt][1] + bb1, 0.f);
            float h2 = fmaxf(d[nt][2] + bb0, 0.f), h3 = fmaxf(d[nt][3] + bb1, 0.f);
            int w0 = (wr + g) * 36 + nt * 4 + t;
            sH[w0]       = packh2(h0, h1);
            sH[w0 + 288] = packh2(h2, h3);
        }
        __syncwarp();

        float d2[8][4];
        #pragma unroll
        for (int i = 0; i < 8; i++)
            #pragma unroll
            for (int j = 0; j < 4; j++) d2[i][j] = 0.0f;

        #pragma unroll 1
        for (int kt = 0; kt < 4; kt++) {
            uint32_t ah[4];
            ldsm_x4(ah, h0a + kt * 32u);
            uint32_t wHi = sbase + N_SW2_HI + bOff36 + kt * 32u;
            uint32_t wLo = sbase + N_SW2_LO + bOff36 + kt * 32u;
            #pragma unroll
            for (int p = 0; p < 4; p++) {
                uint32_t bh[4], bl[4];
                ldsm_x4(bh, wHi + p * 2304u);
                ldsm_x4(bl, wLo + p * 2304u);
                mma16816(d2[2 * p],     ah, bh);
                mma16816(d2[2 * p + 1], ah, bh + 2);
                mma16816(d2[2 * p],     ah, bl);
                mma16816(d2[2 * p + 1], ah, bl + 2);
            }
        }

        {
            int r0 = nbase + wr + g, r1 = r0 + 8;
            bool v0 = r0 < n_nodes, v1 = r1 < n_nodes;
            #pragma unroll
            for (int nt = 0; nt < 8; nt++) {
                int c0 = nt * 8 + 2 * t;
                float bb0 = bias2[c0], bb1 = bias2[c0 + 1];
                if (v0)
                    stg_cs2(feats_out + (size_t)r0 * 64 + c0,
                            d2[nt][0] + bb0, d2[nt][1] + bb1);
                if (v1)
                    stg_cs2(feats_out + (size_t)r1 * 64 + c0,
                            d2[nt][2] + bb0, d2[nt][3] + bb1);
            }
        }
        __syncwarp();
    }
}

// ======================= launch =======================
extern "C" void kernel_launch(void* const* d_in, const int* in_sizes, int n_in,
                              void* d_out, int out_size) {
    const float* feats      = (const float*)d_in[0];
    const int*   edge_index = (const int*)d_in[1];
    const float* edge_attr  = (const float*)d_in[2];
    const float* W1e        = (const float*)d_in[3];
    const float* b1e        = (const float*)d_in[4];
    const float* W2e        = (const float*)d_in[5];
    const float* b2e        = (const float*)d_in[6];
    const float* W1n        = (const float*)d_in[7];
    const float* b1n        = (const float*)d_in[8];
    const float* W2n        = (const float*)d_in[9];
    const float* b2n        = (const float*)d_in[10];

    int n_nodes = in_sizes[0] / 64;
    int n_edges = in_sizes[2] / 64;

    float* out       = (float*)d_out;
    float* feats_out = out;                          // [n_nodes, 64]
    float* e_out     = out + (size_t)n_nodes * 64;   // [n_edges, 64]

    cudaFuncSetAttribute(pnode_kernel, cudaFuncAttributeMaxDynamicSharedMemorySize, P_SMEM);
    cudaFuncSetAttribute(edge_kernel, cudaFuncAttributeMaxDynamicSharedMemorySize, E_SMEM);
    cudaFuncSetAttribute(node_kernel, cudaFuncAttributeMaxDynamicSharedMemorySize, N_SMEM);

    zero_kernel<<<1024, 256>>>(n_nodes);
    pnode_kernel<<<296, 256, P_SMEM>>>(feats, W1e, n_nodes);
    edge_kernel<<<296, 256, E_SMEM>>>(feats, edge_index, edge_attr,
                                      W1e, b1e, W2e, b2e, e_out, n_edges);
    node_kernel<<<148, 256, N_SMEM>>>(feats, W1n, b1n, W2n, b2n,
                                      feats_out, n_nodes);
}

// round 16
// speedup vs baseline: 1.0242x; 1.0016x over previous
#include <cuda_runtime.h>
#include <cuda_fp16.h>
#include <cstdint>

#define MAX_NODES 50000

__device__ float g_agg[MAX_NODES * 64];
__device__ float g_deg[MAX_NODES];
__device__ float g_P[MAX_NODES * 128];   // P[v] = feats[v] @ [W1e[0:64]||W1e[64:128]]

// ---------------- helpers ----------------
__device__ __forceinline__ void mma16816(float d[4], const uint32_t a[4],
                                         const uint32_t b[2]) {
    asm("mma.sync.aligned.m16n8k16.row.col.f32.f16.f16.f32 "
        "{%0,%1,%2,%3}, {%4,%5,%6,%7}, {%8,%9}, {%0,%1,%2,%3};"
        : "+f"(d[0]), "+f"(d[1]), "+f"(d[2]), "+f"(d[3])
        : "r"(a[0]), "r"(a[1]), "r"(a[2]), "r"(a[3]), "r"(b[0]), "r"(b[1]));
}

__device__ __forceinline__ void ldsm_x4(uint32_t r[4], uint32_t addr) {
    asm volatile("ldmatrix.sync.aligned.m8n8.x4.shared.b16 {%0,%1,%2,%3}, [%4];"
        : "=r"(r[0]), "=r"(r[1]), "=r"(r[2]), "=r"(r[3]) : "r"(addr));
}

__device__ __forceinline__ uint32_t packh2(float a, float b) {
    __half2 p = __floats2half2_rn(a, b);
    return *(uint32_t*)&p;
}

__device__ __forceinline__ void wsplit(float w, __half& hh, __half& hl) {
    hh = __float2half_rn(w);
    hl = __float2half_rn(w - __half2float(hh));
}

__device__ __forceinline__ void red_add2(float* addr, float a, float b) {
    asm volatile("red.global.add.v2.f32 [%0], {%1, %2};"
                 :: "l"(addr), "f"(a), "f"(b) : "memory");
}

__device__ __forceinline__ float4 ldg_cs4(const float4* p) {
    float4 v;
    asm volatile("ld.global.cs.v4.f32 {%0,%1,%2,%3}, [%4];"
        : "=f"(v.x), "=f"(v.y), "=f"(v.z), "=f"(v.w) : "l"(p));
    return v;
}
__device__ __forceinline__ void stg_cs2(float* p, float a, float b) {
    asm volatile("st.global.cs.v2.f32 [%0], {%1, %2};"
        :: "l"(p), "f"(a), "f"(b) : "memory");
}

// ---------------- kernel 0: zero scratch ----------------
__global__ void zero_kernel(int n_nodes) {
    int i = blockIdx.x * blockDim.x + threadIdx.x;
    int stride = gridDim.x * blockDim.x;
    int tot = n_nodes * 64;
    for (int k = i; k < tot; k += stride) g_agg[k] = 0.0f;
    for (int k = i; k < n_nodes; k += stride) g_deg[k] = 0.0f;
}

// ======================= P precompute kernel =======================
#define P_SA    0u
#define P_SW_HI 18432u
#define P_SW_LO 36864u
#define P_SMEM  55296u

__global__ void __launch_bounds__(256, 2) pnode_kernel(
    const float* __restrict__ feats,
    const float* __restrict__ W1e,
    int n_nodes)
{
    extern __shared__ char smem[];
    uint32_t* sA = (uint32_t*)(smem + P_SA);

    int tid = threadIdx.x;
    for (int i = tid; i < 128 * 64; i += 256) {
        int n = i & 127, k = i >> 7;
        float w = (n < 64) ? W1e[k * 64 + n] : W1e[(64 + k) * 64 + (n - 64)];
        __half wh, wl;
        wsplit(w, wh, wl);
        ((__half*)(smem + P_SW_HI))[n * 72 + k] = wh;
        ((__half*)(smem + P_SW_LO))[n * 72 + k] = wl;
    }
    __syncthreads();

    const int warp = tid >> 5, lane = tid & 31;
    const int g = lane >> 2, t = lane & 3;
    const int wr = warp << 4;

    const int r8 = lane & 7;
    const int m01 = (lane >> 3) & 1;
    const int q01 = lane >> 4;
    uint32_t sbase = (uint32_t)__cvta_generic_to_shared(smem);
    uint32_t a0 = sbase + P_SA + ((uint32_t)(wr + r8 + m01 * 8) * 36u + q01 * 4u) * 4u;
    uint32_t bOff = ((uint32_t)(q01 * 8 + r8) * 36u + m01 * 4u) * 4u;

    int nTiles = (n_nodes + 127) >> 7;

    for (int tile = blockIdx.x; tile < nTiles; tile += gridDim.x) {
        int nbase = tile << 7;
        {
            size_t base4 = (size_t)(nbase + wr) * 16;
            size_t max4 = (size_t)n_nodes * 16 - 1;
            #pragma unroll
            for (int j = 0; j < 8; j++) {
                int idx = j * 32 + lane;
                size_t gidx = base4 + idx; if (gidx > max4) gidx = max4;
                float4 va = ((const float4*)feats)[gidx];
                int rloc = wr + (idx >> 4);
                int c4 = idx & 15;
                *(uint2*)(sA + rloc * 36 + c4 * 2) =
                    make_uint2(packh2(va.x, va.y), packh2(va.z, va.w));
            }
        }
        __syncwarp();

        float d[16][4];
        #pragma unroll
        for (int i = 0; i < 16; i++)
            #pragma unroll
            for (int j = 0; j < 4; j++) d[i][j] = 0.0f;

        #pragma unroll 1
        for (int kt = 0; kt < 4; kt++) {
            uint32_t ah[4];
            ldsm_x4(ah, a0 + kt * 32u);
            uint32_t wHi = sbase + P_SW_HI + bOff + kt * 32u;
            uint32_t wLo = sbase + P_SW_LO + bOff + kt * 32u;
            #pragma unroll
            for (int p = 0; p < 8; p++) {
                uint32_t bh[4], bl[4];
                ldsm_x4(bh, wHi + p * 2304u);
                ldsm_x4(bl, wLo + p * 2304u);
                mma16816(d[2 * p],     ah, bh);
                mma16816(d[2 * p + 1], ah, bh + 2);
                mma16816(d[2 * p],     ah, bl);
                mma16816(d[2 * p + 1], ah, bl + 2);
            }
        }

        {
            int r0 = nbase + wr + g, r1 = r0 + 8;
            bool v0 = r0 < n_nodes, v1 = r1 < n_nodes;
            #pragma unroll
            for (int nt = 0; nt < 16; nt++) {
                int c0 = nt * 8 + 2 * t;
                if (v0) *(float2*)(g_P + (size_t)r0 * 128 + c0) =
                            make_float2(d[nt][0], d[nt][1]);
                if (v1) *(float2*)(g_P + (size_t)r1 * 128 + c0) =
                            make_float2(d[nt][2], d[nt][3]);
            }
        }
        __syncwarp();
    }
}

// ======================= edge kernel =======================
#define E_SA      0u
#define E_SW1_HI  18432u
#define E_SW1_LO  27648u
#define E_SH      36864u
#define E_SW2_HI  55296u
#define E_SW2_LO  64512u
#define E_BIAS1   73728u
#define E_BIAS2   73984u
#define E_SR      74240u
#define E_SC      74752u
#define E_SMEM    75264u

__global__ void __launch_bounds__(256, 2) edge_kernel(
    const float* __restrict__ feats,
    const int* __restrict__ edge_index,
    const float* __restrict__ edge_attr,
    const float* __restrict__ W1e, const float* __restrict__ b1e,
    const float* __restrict__ W2e, const float* __restrict__ b2e,
    float* __restrict__ e_out,
    int n_edges)
{
    extern __shared__ char smem[];
    uint32_t* sA = (uint32_t*)(smem + E_SA);
    uint32_t* sH = (uint32_t*)(smem + E_SH);
    float* bias1 = (float*)(smem + E_BIAS1);
    float* bias2 = (float*)(smem + E_BIAS2);
    int*   sr    = (int*)(smem + E_SR);
    int*   sc    = (int*)(smem + E_SC);

    int tid = threadIdx.x;

    for (int i = tid; i < 64 * 64; i += 256) {
        int k = i >> 6, n = i & 63;
        float w = W1e[(128 + k) * 64 + n];
        __half wh, wl;
        wsplit(w, wh, wl);
        ((__half*)(smem + E_SW1_HI))[n * 72 + k] = wh;
        ((__half*)(smem + E_SW1_LO))[n * 72 + k] = wl;
    }
    for (int i = tid; i < 64 * 64; i += 256) {
        int k = i >> 6, n = i & 63;
        float w = W2e[i];
        __half wh, wl;
        wsplit(w, wh, wl);
        ((__half*)(smem + E_SW2_HI))[n * 72 + k] = wh;
        ((__half*)(smem + E_SW2_LO))[n * 72 + k] = wl;
    }
    if (tid < 64) {
        bias1[tid] = b1e[tid];
        bias2[tid] = b2e[tid];
    }
    __syncthreads();

    const int warp = tid >> 5, lane = tid & 31;
    const int g = lane >> 2, t = lane & 3;
    const int wr = warp << 4;
    const int row = tid >> 1, half = tid & 1;

    const int r8 = lane & 7;
    const int m01 = (lane >> 3) & 1;
    const int q01 = lane >> 4;
    uint32_t sbase = (uint32_t)__cvta_generic_to_shared(smem);
    uint32_t fragRow = ((uint32_t)(wr + r8 + m01 * 8) * 36u + q01 * 4u) * 4u;
    uint32_t a0 = sbase + E_SA + fragRow;
    uint32_t h0a = sbase + E_SH + fragRow;
    uint32_t bOff = ((uint32_t)(q01 * 8 + r8) * 36u + m01 * 4u) * 4u;

    int nTiles = (n_edges + 127) >> 7;
    int tstride = gridDim.x;
    size_t max4 = (size_t)n_edges * 16 - 1;

    // ---- preload first tile's edge_attr (packed fp16) into registers ----
    uint2 buf[8];
    int tile = blockIdx.x;
    if (tile < nTiles) {
        size_t base4 = (size_t)((tile << 7) + wr) * 16;
        #pragma unroll
        for (int j = 0; j < 8; j++) {
            int idx = j * 32 + lane;
            size_t gidx = base4 + idx; if (gidx > max4) gidx = max4;
            float4 va = ldg_cs4((const float4*)edge_attr + gidx);
            buf[j] = make_uint2(packh2(va.x, va.y), packh2(va.z, va.w));
        }
    }

    for (; tile < nTiles; tile += tstride) {
        int ebase = tile << 7;

        // ---- indices + deg ----
        {
            int er = ebase + row;
            bool v = er < n_edges;
            int eid = v ? er : (n_edges - 1);
            if (half == 0) {
                int2 rc = ((const int2*)edge_index)[eid];
                sr[row] = rc.x;
                sc[row] = rc.y;
                if (v) atomicAdd(&g_deg[rc.y], 1.0f);
            }
        }
        // ---- stage prefetched tile to smem ----
        {
            #pragma unroll
            for (int j = 0; j < 8; j++) {
                int idx = j * 32 + lane;
                int rloc = wr + (idx >> 4);
                int c4 = idx & 15;
                *(uint2*)(sA + rloc * 36 + c4 * 2) = buf[j];
            }
        }
        __syncwarp();

        // ---- prefetch NEXT tile's edge_attr (latency hides behind GEMM1/epi1) ----
        {
            int tn = tile + tstride;
            if (tn < nTiles) {
                size_t base4 = (size_t)((tn << 7) + wr) * 16;
                #pragma unroll
                for (int j = 0; j < 8; j++) {
                    int idx = j * 32 + lane;
                    size_t gidx = base4 + idx; if (gidx > max4) gidx = max4;
                    float4 va = ldg_cs4((const float4*)edge_attr + gidx);
                    buf[j] = make_uint2(packh2(va.x, va.y), packh2(va.z, va.w));
                }
            }
        }

        // ---- GEMM1: edge_attr @ W1c, K=64 (fp16 2-pass) ----
        float d[8][4];
        #pragma unroll
        for (int i = 0; i < 8; i++)
            #pragma unroll
            for (int j = 0; j < 4; j++) d[i][j] = 0.0f;

        #pragma unroll 1
        for (int kt = 0; kt < 4; kt++) {
            uint32_t ah[4];
            ldsm_x4(ah, a0 + kt * 32u);
            uint32_t wHi = sbase + E_SW1_HI + bOff + kt * 32u;
            uint32_t wLo = sbase + E_SW1_LO + bOff + kt * 32u;
            #pragma unroll
            for (int p = 0; p < 4; p++) {
                uint32_t bh[4], bl[4];
                ldsm_x4(bh, wHi + p * 2304u);
                ldsm_x4(bl, wLo + p * 2304u);
                mma16816(d[2 * p],     ah, bh);
                mma16816(d[2 * p + 1], ah, bh + 2);
                mma16816(d[2 * p],     ah, bl);
                mma16816(d[2 * p + 1], ah, bl + 2);
            }
        }

        // ---- epilogue 1: h = relu(d + P[r][c] + P[c][64+c] + b1) -> sH (hi only) ----
        {
            int rr0 = sr[wr + g],     cc0 = sc[wr + g];
            int rr1 = sr[wr + 8 + g], cc1 = sc[wr + 8 + g];
            const float* P0r = g_P + (size_t)rr0 * 128;
            const float* P0c = g_P + (size_t)cc0 * 128 + 64;
            const float* P1r = g_P + (size_t)rr1 * 128;
            const float* P1c = g_P + (size_t)cc1 * 128 + 64;
            #pragma unroll
            for (int nt = 0; nt < 8; nt++) {
                int c0 = nt * 8 + 2 * t;
                float2 pa = *(const float2*)(P0r + c0);
                float2 pb = *(const float2*)(P0c + c0);
                float2 pc_ = *(const float2*)(P1r + c0);
                float2 pd = *(const float2*)(P1c + c0);
                float bb0 = bias1[c0], bb1 = bias1[c0 + 1];
                float h0 = fmaxf(d[nt][0] + pa.x + pb.x + bb0, 0.f);
                float h1 = fmaxf(d[nt][1] + pa.y + pb.y + bb1, 0.f);
                float h2 = fmaxf(d[nt][2] + pc_.x + pd.x + bb0, 0.f);
                float h3 = fmaxf(d[nt][3] + pc_.y + pd.y + bb1, 0.f);
                int w0 = (wr + g) * 36 + nt * 4 + t;
                sH[w0]       = packh2(h0, h1);
                sH[w0 + 288] = packh2(h2, h3);
            }
        }
        __syncwarp();

        // ---- GEMM2: K=64 (fp16 2-pass) ----
        float d2[8][4];
        #pragma unroll
        for (int i = 0; i < 8; i++)
            #pragma unroll
            for (int j = 0; j < 4; j++) d2[i][j] = 0.0f;

        #pragma unroll 1
        for (int kt = 0; kt < 4; kt++) {
            uint32_t ah[4];
            ldsm_x4(ah, h0a + kt * 32u);
            uint32_t wHi = sbase + E_SW2_HI + bOff + kt * 32u;
            uint32_t wLo = sbase + E_SW2_LO + bOff + kt * 32u;
            #pragma unroll
            for (int p = 0; p < 4; p++) {
                uint32_t bh[4], bl[4];
                ldsm_x4(bh, wHi + p * 2304u);
                ldsm_x4(bl, wLo + p * 2304u);
                mma16816(d2[2 * p],     ah, bh);
                mma16816(d2[2 * p + 1], ah, bh + 2);
                mma16816(d2[2 * p],     ah, bl);
                mma16816(d2[2 * p + 1], ah, bl + 2);
            }
        }

        // ---- epilogue 2: e = D2 + b2 -> e_out (streaming) + red to g_agg ----
        {
            int r0 = ebase + wr + g, r1 = r0 + 8;
            bool v0 = r0 < n_edges, v1 = r1 < n_edges;
            int ca = sc[wr + g], cb = sc[wr + 8 + g];
            #pragma unroll
            for (int nt = 0; nt < 8; nt++) {
                int c0 = nt * 8 + 2 * t;
                float bb0 = bias2[c0], bb1 = bias2[c0 + 1];
                float e0 = d2[nt][0] + bb0, e1 = d2[nt][1] + bb1;
                float e2 = d2[nt][2] + bb0, e3 = d2[nt][3] + bb1;
                if (v0) {
                    stg_cs2(e_out + (size_t)r0 * 64 + c0, e0, e1);
                    red_add2(g_agg + (size_t)ca * 64 + c0, e0, e1);
                }
                if (v1) {
                    stg_cs2(e_out + (size_t)r1 * 64 + c0, e2, e3);
                    red_add2(g_agg + (size_t)cb * 64 + c0, e2, e3);
                }
            }
        }
        __syncwarp();
    }
}

// ======================= node kernel =======================
#define N_SA      0u
#define N_SW1_HI  34816u
#define N_SW1_LO  52224u
#define N_SH      69632u
#define N_SW2_HI  88064u
#define N_SW2_LO  97280u
#define N_BIAS1   106496u
#define N_BIAS2   106752u
#define N_SMEM    107008u

__global__ void __launch_bounds__(256, 1) node_kernel(
    const float* __restrict__ feats,
    const float* __restrict__ W1n, const float* __restrict__ b1n,
    const float* __restrict__ W2n, const float* __restrict__ b2n,
    float* __restrict__ feats_out,
    int n_nodes)
{
    extern __shared__ char smem[];
    uint32_t* sA = (uint32_t*)(smem + N_SA);
    uint32_t* sH = (uint32_t*)(smem + N_SH);
    float* bias1 = (float*)(smem + N_BIAS1);
    float* bias2 = (float*)(smem + N_BIAS2);

    int tid = threadIdx.x;

    for (int i = tid; i < 128 * 64; i += 256) {
        int k = i >> 6, n = i & 63;
        float w = W1n[i];
        __half wh, wl;
        wsplit(w, wh, wl);
        ((__half*)(smem + N_SW1_HI))[n * 136 + k] = wh;
        ((__half*)(smem + N_SW1_LO))[n * 136 + k] = wl;
    }
    for (int i = tid; i < 64 * 64; i += 256) {
        int k = i >> 6, n = i & 63;
        float w = W2n[i];
        __half wh, wl;
        wsplit(w, wh, wl);
        ((__half*)(smem + N_SW2_HI))[n * 72 + k] = wh;
        ((__half*)(smem + N_SW2_LO))[n * 72 + k] = wl;
    }
    if (tid < 64) {
        bias1[tid] = b1n[tid];
        bias2[tid] = b2n[tid];
    }
    __syncthreads();

    const int warp = tid >> 5, lane = tid & 31;
    const int g = lane >> 2, t = lane & 3;
    const int wr = warp << 4;

    const int r8 = lane & 7;
    const int m01 = (lane >> 3) & 1;
    const int q01 = lane >> 4;
    uint32_t sbase = (uint32_t)__cvta_generic_to_shared(smem);
    uint32_t a0 = sbase + N_SA + ((uint32_t)(wr + r8 + m01 * 8) * 68u + q01 * 4u) * 4u;
    uint32_t fragRow36 = ((uint32_t)(wr + r8 + m01 * 8) * 36u + q01 * 4u) * 4u;
    uint32_t h0a = sbase + N_SH + fragRow36;
    uint32_t bOff68 = ((uint32_t)(q01 * 8 + r8) * 68u + m01 * 4u) * 4u;
    uint32_t bOff36 = ((uint32_t)(q01 * 8 + r8) * 36u + m01 * 4u) * 4u;

    int nTiles = (n_nodes + 127) >> 7;

    for (int tile = blockIdx.x; tile < nTiles; tile += gridDim.x) {
        int nbase = tile << 7;

        {
            float invdReg;
            {
                int r16 = nbase + wr + (lane & 15);
                int nid = r16 < n_nodes ? r16 : (n_nodes - 1);
                invdReg = 1.0f / fmaxf(g_deg[nid], 1.0f);
            }
            size_t base4 = (size_t)(nbase + wr) * 16;
            size_t max4 = (size_t)n_nodes * 16 - 1;
            #pragma unroll
            for (int j = 0; j < 8; j++) {
                int idx = j * 32 + lane;
                size_t gidx = base4 + idx; if (gidx > max4) gidx = max4;
                float4 va = ((const float4*)feats)[gidx];
                int rloc = wr + (idx >> 4);
                int c4 = idx & 15;
                *(uint2*)(sA + rloc * 68 + c4 * 2) =
                    make_uint2(packh2(va.x, va.y), packh2(va.z, va.w));
            }
            #pragma unroll
            for (int j = 0; j < 8; j++) {
                int idx = j * 32 + lane;
                size_t gidx = base4 + idx; if (gidx > max4) gidx = max4;
                float4 va = ((const float4*)g_agg)[gidx];
                float s = __shfl_sync(0xffffffffu, invdReg, idx >> 4);
                va.x *= s; va.y *= s; va.z *= s; va.w *= s;
                int rloc = wr + (idx >> 4);
                int c4 = idx & 15;
                *(uint2*)(sA + rloc * 68 + 32 + c4 * 2) =
                    make_uint2(packh2(va.x, va.y), packh2(va.z, va.w));
            }
        }
        __syncwarp();

        float d[8][4];
        #pragma unroll
        for (int i = 0; i < 8; i++)
            #pragma unroll
            for (int j = 0; j < 4; j++) d[i][j] = 0.0f;

        #pragma unroll 1
        for (int kt = 0; kt < 8; kt++) {
            uint32_t ah[4];
            ldsm_x4(ah, a0 + kt * 32u);
            uint32_t wHi = sbase + N_SW1_HI + bOff68 + kt * 32u;
            uint32_t wLo = sbase + N_SW1_LO + bOff68 + kt * 32u;
            #pragma unroll
            for (int p = 0; p < 4; p++) {
                uint32_t bh[4], bl[4];
                ldsm_x4(bh, wHi + p * 4352u);
                ldsm_x4(bl, wLo + p * 4352u);
                mma16816(d[2 * p],     ah, bh);
                mma16816(d[2 * p + 1], ah, bh + 2);
                mma16816(d[2 * p],     ah, bl);
                mma16816(d[2 * p + 1], ah, bl + 2);
            }
        }

        #pragma unroll
        for (int nt = 0; nt < 8; nt++) {
            int c0 = nt * 8 + 2 * t;
            float bb0 = bias1[c0], bb1 = bias1[c0 + 1];
            float h0 = fmaxf(d[nt][0] + bb0, 0.f), h1 = fmaxf(d[nt][1] + bb1, 0.f);
            float h2 = fmaxf(d[nt][2] + bb0, 0.f), h3 = fmaxf(d[nt][3] + bb1, 0.f);
            int w0 = (wr + g) * 36 + nt * 4 + t;
            sH[w0]       = packh2(h0, h1);
            sH[w0 + 288] = packh2(h2, h3);
        }
        __syncwarp();

        float d2[8][4];
        #pragma unroll
        for (int i = 0; i < 8; i++)
            #pragma unroll
            for (int j = 0; j < 4; j++) d2[i][j] = 0.0f;

        #pragma unroll 1
        for (int kt = 0; kt < 4; kt++) {
            uint32_t ah[4];
            ldsm_x4(ah, h0a + kt * 32u);
            uint32_t wHi = sbase + N_SW2_HI + bOff36 + kt * 32u;
            uint32_t wLo = sbase + N_SW2_LO + bOff36 + kt * 32u;
            #pragma unroll
            for (int p = 0; p < 4; p++) {
                uint32_t bh[4], bl[4];
                ldsm_x4(bh, wHi + p * 2304u);
                ldsm_x4(bl, wLo + p * 2304u);
                mma16816(d2[2 * p],     ah, bh);
                mma16816(d2[2 * p + 1], ah, bh + 2);
                mma16816(d2[2 * p],     ah, bl);
                mma16816(d2[2 * p + 1], ah, bl + 2);
            }
        }

        {
            int r0 = nbase + wr + g, r1 = r0 + 8;
            bool v0 = r0 < n_nodes, v1 = r1 < n_nodes;
            #pragma unroll
            for (int nt = 0; nt < 8; nt++) {
                int c0 = nt * 8 + 2 * t;
                float bb0 = bias2[c0], bb1 = bias2[c0 + 1];
                if (v0)
                    stg_cs2(feats_out + (size_t)r0 * 64 + c0,
                            d2[nt][0] + bb0, d2[nt][1] + bb1);
                if (v1)
                    stg_cs2(feats_out + (size_t)r1 * 64 + c0,
                            d2[nt][2] + bb0, d2[nt][3] + bb1);
            }
        }
        __syncwarp();
    }
}

// ======================= launch =======================
extern "C" void kernel_launch(void* const* d_in, const int* in_sizes, int n_in,
                              void* d_out, int out_size) {
    const float* feats      = (const float*)d_in[0];
    const int*   edge_index = (const int*)d_in[1];
    const float* edge_attr  = (const float*)d_in[2];
    const float* W1e        = (const float*)d_in[3];
    const float* b1e        = (const float*)d_in[4];
    const float* W2e        = (const float*)d_in[5];
    const float* b2e        = (const float*)d_in[6];
    const float* W1n        = (const float*)d_in[7];
    const float* b1n        = (const float*)d_in[8];
    const float* W2n        = (const float*)d_in[9];
    const float* b2n        = (const float*)d_in[10];

    int n_nodes = in_sizes[0] / 64;
    int n_edges = in_sizes[2] / 64;

    float* out       = (float*)d_out;
    float* feats_out = out;                          // [n_nodes, 64]
    float* e_out     = out + (size_t)n_nodes * 64;   // [n_edges, 64]

    cudaFuncSetAttribute(pnode_kernel, cudaFuncAttributeMaxDynamicSharedMemorySize, P_SMEM);
    cudaFuncSetAttribute(edge_kernel, cudaFuncAttributeMaxDynamicSharedMemorySize, E_SMEM);
    cudaFuncSetAttribute(node_kernel, cudaFuncAttributeMaxDynamicSharedMemorySize, N_SMEM);

    zero_kernel<<<1024, 256>>>(n_nodes);
    pnode_kernel<<<296, 256, P_SMEM>>>(feats, W1e, n_nodes);
    edge_kernel<<<296, 256, E_SMEM>>>(feats, edge_index, edge_attr,
                                      W1e, b1e, W2e, b2e, e_out, n_edges);
    node_kernel<<<148, 256, N_SMEM>>>(feats, W1n, b1n, W2n, b2n,
                                      feats_out, n_nodes);
}

// round 17
// speedup vs baseline: 1.0652x; 1.0400x over previous
#include <cuda_runtime.h>
#include <cuda_fp16.h>
#include <cstdint>

#define MAX_NODES 50000

__device__ float g_agg[MAX_NODES * 64];
__device__ float g_deg[MAX_NODES];
__device__ float g_P[MAX_NODES * 128];   // P[v] = feats[v] @ [W1e[0:64]||W1e[64:128]]

// ---------------- helpers ----------------
__device__ __forceinline__ void mma16816(float d[4], const uint32_t a[4],
                                         const uint32_t b[2]) {
    asm("mma.sync.aligned.m16n8k16.row.col.f32.f16.f16.f32 "
        "{%0,%1,%2,%3}, {%4,%5,%6,%7}, {%8,%9}, {%0,%1,%2,%3};"
        : "+f"(d[0]), "+f"(d[1]), "+f"(d[2]), "+f"(d[3])
        : "r"(a[0]), "r"(a[1]), "r"(a[2]), "r"(a[3]), "r"(b[0]), "r"(b[1]));
}

__device__ __forceinline__ void ldsm_x4(uint32_t r[4], uint32_t addr) {
    asm volatile("ldmatrix.sync.aligned.m8n8.x4.shared.b16 {%0,%1,%2,%3}, [%4];"
        : "=r"(r[0]), "=r"(r[1]), "=r"(r[2]), "=r"(r[3]) : "r"(addr));
}

__device__ __forceinline__ uint32_t packh2(float a, float b) {
    __half2 p = __floats2half2_rn(a, b);
    return *(uint32_t*)&p;
}

__device__ __forceinline__ void wsplit(float w, __half& hh, __half& hl) {
    hh = __float2half_rn(w);
    hl = __float2half_rn(w - __half2float(hh));
}

__device__ __forceinline__ void red_add2(float* addr, float a, float b) {
    asm volatile("red.global.add.v2.f32 [%0], {%1, %2};"
                 :: "l"(addr), "f"(a), "f"(b) : "memory");
}

__device__ __forceinline__ float4 ldg_cs4(const float4* p) {
    float4 v;
    asm volatile("ld.global.cs.v4.f32 {%0,%1,%2,%3}, [%4];"
        : "=f"(v.x), "=f"(v.y), "=f"(v.z), "=f"(v.w) : "l"(p));
    return v;
}
__device__ __forceinline__ void stg_cs2(float* p, float a, float b) {
    asm volatile("st.global.cs.v2.f32 [%0], {%1, %2};"
        :: "l"(p), "f"(a), "f"(b) : "memory");
}
__device__ __forceinline__ void stg_cs4(float* p, float4 v) {
    asm volatile("st.global.cs.v4.f32 [%0], {%1, %2, %3, %4};"
        :: "l"(p), "f"(v.x), "f"(v.y), "f"(v.z), "f"(v.w) : "memory");
}

// ---------------- kernel 0: zero scratch ----------------
__global__ void zero_kernel(int n_nodes) {
    int i = blockIdx.x * blockDim.x + threadIdx.x;
    int stride = gridDim.x * blockDim.x;
    int tot = n_nodes * 64;
    for (int k = i; k < tot; k += stride) g_agg[k] = 0.0f;
    for (int k = i; k < n_nodes; k += stride) g_deg[k] = 0.0f;
}

// ======================= P precompute kernel =======================
#define P_SA    0u
#define P_SW_HI 18432u
#define P_SW_LO 36864u
#define P_SMEM  55296u

__global__ void __launch_bounds__(256, 2) pnode_kernel(
    const float* __restrict__ feats,
    const float* __restrict__ W1e,
    int n_nodes)
{
    extern __shared__ char smem[];
    uint32_t* sA = (uint32_t*)(smem + P_SA);

    int tid = threadIdx.x;
    for (int i = tid; i < 128 * 64; i += 256) {
        int n = i & 127, k = i >> 7;
        float w = (n < 64) ? W1e[k * 64 + n] : W1e[(64 + k) * 64 + (n - 64)];
        __half wh, wl;
        wsplit(w, wh, wl);
        ((__half*)(smem + P_SW_HI))[n * 72 + k] = wh;
        ((__half*)(smem + P_SW_LO))[n * 72 + k] = wl;
    }
    __syncthreads();

    const int warp = tid >> 5, lane = tid & 31;
    const int g = lane >> 2, t = lane & 3;
    const int wr = warp << 4;

    const int r8 = lane & 7;
    const int m01 = (lane >> 3) & 1;
    const int q01 = lane >> 4;
    uint32_t sbase = (uint32_t)__cvta_generic_to_shared(smem);
    uint32_t a0 = sbase + P_SA + ((uint32_t)(wr + r8 + m01 * 8) * 36u + q01 * 4u) * 4u;
    uint32_t bOff = ((uint32_t)(q01 * 8 + r8) * 36u + m01 * 4u) * 4u;

    int nTiles = (n_nodes + 127) >> 7;

    for (int tile = blockIdx.x; tile < nTiles; tile += gridDim.x) {
        int nbase = tile << 7;
        {
            size_t base4 = (size_t)(nbase + wr) * 16;
            size_t max4 = (size_t)n_nodes * 16 - 1;
            #pragma unroll
            for (int j = 0; j < 8; j++) {
                int idx = j * 32 + lane;
                size_t gidx = base4 + idx; if (gidx > max4) gidx = max4;
                float4 va = ((const float4*)feats)[gidx];
                int rloc = wr + (idx >> 4);
                int c4 = idx & 15;
                *(uint2*)(sA + rloc * 36 + c4 * 2) =
                    make_uint2(packh2(va.x, va.y), packh2(va.z, va.w));
            }
        }
        __syncwarp();

        float d[16][4];
        #pragma unroll
        for (int i = 0; i < 16; i++)
            #pragma unroll
            for (int j = 0; j < 4; j++) d[i][j] = 0.0f;

        #pragma unroll 1
        for (int kt = 0; kt < 4; kt++) {
            uint32_t ah[4];
            ldsm_x4(ah, a0 + kt * 32u);
            uint32_t wHi = sbase + P_SW_HI + bOff + kt * 32u;
            uint32_t wLo = sbase + P_SW_LO + bOff + kt * 32u;
            #pragma unroll
            for (int p = 0; p < 8; p++) {
                uint32_t bh[4], bl[4];
                ldsm_x4(bh, wHi + p * 2304u);
                ldsm_x4(bl, wLo + p * 2304u);
                mma16816(d[2 * p],     ah, bh);
                mma16816(d[2 * p + 1], ah, bh + 2);
                mma16816(d[2 * p],     ah, bl);
                mma16816(d[2 * p + 1], ah, bl + 2);
            }
        }

        {
            int r0 = nbase + wr + g, r1 = r0 + 8;
            bool v0 = r0 < n_nodes, v1 = r1 < n_nodes;
            #pragma unroll
            for (int nt = 0; nt < 16; nt++) {
                int c0 = nt * 8 + 2 * t;
                if (v0) *(float2*)(g_P + (size_t)r0 * 128 + c0) =
                            make_float2(d[nt][0], d[nt][1]);
                if (v1) *(float2*)(g_P + (size_t)r1 * 128 + c0) =
                            make_float2(d[nt][2], d[nt][3]);
            }
        }
        __syncwarp();
    }
}

// ======================= edge kernel =======================
#define E_SA      0u
#define E_SW1_HI  18432u
#define E_SW1_LO  27648u
#define E_SH      36864u
#define E_SW2_HI  55296u
#define E_SW2_LO  64512u
#define E_BIAS1   73728u
#define E_BIAS2   73984u
#define E_SR      74240u
#define E_SC      74752u
#define E_STG     75264u            // [128 rows][68 floats] = 34816 B
#define E_SMEM    110080u

__global__ void __launch_bounds__(256, 2) edge_kernel(
    const float* __restrict__ feats,
    const int* __restrict__ edge_index,
    const float* __restrict__ edge_attr,
    const float* __restrict__ W1e, const float* __restrict__ b1e,
    const float* __restrict__ W2e, const float* __restrict__ b2e,
    float* __restrict__ e_out,
    int n_edges)
{
    extern __shared__ char smem[];
    uint32_t* sA = (uint32_t*)(smem + E_SA);
    uint32_t* sH = (uint32_t*)(smem + E_SH);
    float* bias1 = (float*)(smem + E_BIAS1);
    float* bias2 = (float*)(smem + E_BIAS2);
    int*   sr    = (int*)(smem + E_SR);
    int*   sc    = (int*)(smem + E_SC);
    float* stg   = (float*)(smem + E_STG);   // [128][68]

    int tid = threadIdx.x;

    for (int i = tid; i < 64 * 64; i += 256) {
        int k = i >> 6, n = i & 63;
        float w = W1e[(128 + k) * 64 + n];
        __half wh, wl;
        wsplit(w, wh, wl);
        ((__half*)(smem + E_SW1_HI))[n * 72 + k] = wh;
        ((__half*)(smem + E_SW1_LO))[n * 72 + k] = wl;
    }
    for (int i = tid; i < 64 * 64; i += 256) {
        int k = i >> 6, n = i & 63;
        float w = W2e[i];
        __half wh, wl;
        wsplit(w, wh, wl);
        ((__half*)(smem + E_SW2_HI))[n * 72 + k] = wh;
        ((__half*)(smem + E_SW2_LO))[n * 72 + k] = wl;
    }
    if (tid < 64) {
        bias1[tid] = b1e[tid];
        bias2[tid] = b2e[tid];
    }
    __syncthreads();

    const int warp = tid >> 5, lane = tid & 31;
    const int g = lane >> 2, t = lane & 3;
    const int wr = warp << 4;
    const int row = tid >> 1, half = tid & 1;

    const int r8 = lane & 7;
    const int m01 = (lane >> 3) & 1;
    const int q01 = lane >> 4;
    uint32_t sbase = (uint32_t)__cvta_generic_to_shared(smem);
    uint32_t fragRow = ((uint32_t)(wr + r8 + m01 * 8) * 36u + q01 * 4u) * 4u;
    uint32_t a0 = sbase + E_SA + fragRow;
    uint32_t h0a = sbase + E_SH + fragRow;
    uint32_t bOff = ((uint32_t)(q01 * 8 + r8) * 36u + m01 * 4u) * 4u;

    // coalesced staging lane roles: 8 lanes own one 128B line
    const int grp = lane >> 3;       // 0..3
    const int g2  = grp >> 1;        // edge parity
    const int hf  = grp & 1;         // half (cols 0-31 vs 32-63)
    const int c8  = (lane & 7) * 4;  // float offset within half

    int nTiles = (n_edges + 127) >> 7;
    int tstride = gridDim.x;
    size_t max4 = (size_t)n_edges * 16 - 1;

    // ---- preload first tile's edge_attr (packed fp16) into registers ----
    uint2 buf[8];
    int tile = blockIdx.x;
    if (tile < nTiles) {
        size_t base4 = (size_t)((tile << 7) + wr) * 16;
        #pragma unroll
        for (int j = 0; j < 8; j++) {
            int idx = j * 32 + lane;
            size_t gidx = base4 + idx; if (gidx > max4) gidx = max4;
            float4 va = ldg_cs4((const float4*)edge_attr + gidx);
            buf[j] = make_uint2(packh2(va.x, va.y), packh2(va.z, va.w));
        }
    }

    for (; tile < nTiles; tile += tstride) {
        int ebase = tile << 7;

        // ---- indices + deg ----
        {
            int er = ebase + row;
            bool v = er < n_edges;
            int eid = v ? er : (n_edges - 1);
            if (half == 0) {
                int2 rc = ((const int2*)edge_index)[eid];
                sr[row] = rc.x;
                sc[row] = rc.y;
                if (v) atomicAdd(&g_deg[rc.y], 1.0f);
            }
        }
        // ---- stage prefetched tile to smem ----
        {
            #pragma unroll
            for (int j = 0; j < 8; j++) {
                int idx = j * 32 + lane;
                int rloc = wr + (idx >> 4);
                int c4 = idx & 15;
                *(uint2*)(sA + rloc * 36 + c4 * 2) = buf[j];
            }
        }
        __syncwarp();

        // ---- prefetch NEXT tile's edge_attr ----
        {
            int tn = tile + tstride;
            if (tn < nTiles) {
                size_t base4 = (size_t)((tn << 7) + wr) * 16;
                #pragma unroll
                for (int j = 0; j < 8; j++) {
                    int idx = j * 32 + lane;
                    size_t gidx = base4 + idx; if (gidx > max4) gidx = max4;
                    float4 va = ldg_cs4((const float4*)edge_attr + gidx);
                    buf[j] = make_uint2(packh2(va.x, va.y), packh2(va.z, va.w));
                }
            }
        }

        // ---- GEMM1: edge_attr @ W1c, K=64 (fp16 2-pass) ----
        float d[8][4];
        #pragma unroll
        for (int i = 0; i < 8; i++)
            #pragma unroll
            for (int j = 0; j < 4; j++) d[i][j] = 0.0f;

        #pragma unroll 1
        for (int kt = 0; kt < 4; kt++) {
            uint32_t ah[4];
            ldsm_x4(ah, a0 + kt * 32u);
            uint32_t wHi = sbase + E_SW1_HI + bOff + kt * 32u;
            uint32_t wLo = sbase + E_SW1_LO + bOff + kt * 32u;
            #pragma unroll
            for (int p = 0; p < 4; p++) {
                uint32_t bh[4], bl[4];
                ldsm_x4(bh, wHi + p * 2304u);
                ldsm_x4(bl, wLo + p * 2304u);
                mma16816(d[2 * p],     ah, bh);
                mma16816(d[2 * p + 1], ah, bh + 2);
                mma16816(d[2 * p],     ah, bl);
                mma16816(d[2 * p + 1], ah, bl + 2);
            }
        }

        // ---- stage P sums coalesced into stg (64 wf vs 256 scattered) ----
        {
            #pragma unroll
            for (int i = 0; i < 8; i++) {
                int rw = wr + 2 * i + g2;
                int rn = sr[rw], cn = sc[rw];
                float4 v0 = *(const float4*)(g_P + (size_t)rn * 128 + hf * 32 + c8);
                float4 v1 = *(const float4*)(g_P + (size_t)cn * 128 + 64 + hf * 32 + c8);
                *(float4*)(stg + rw * 68 + hf * 32 + c8) =
                    make_float4(v0.x + v1.x, v0.y + v1.y, v0.z + v1.z, v0.w + v1.w);
            }
        }
        __syncwarp();

        // ---- epilogue 1: h = relu(d + Psum + b1) -> sH (hi only) ----
        {
            #pragma unroll
            for (int nt = 0; nt < 8; nt++) {
                int c0 = nt * 8 + 2 * t;
                float2 p0 = *(const float2*)(stg + (wr + g) * 68 + c0);
                float2 p1 = *(const float2*)(stg + (wr + 8 + g) * 68 + c0);
                float bb0 = bias1[c0], bb1 = bias1[c0 + 1];
                float h0 = fmaxf(d[nt][0] + p0.x + bb0, 0.f);
                float h1 = fmaxf(d[nt][1] + p0.y + bb1, 0.f);
                float h2 = fmaxf(d[nt][2] + p1.x + bb0, 0.f);
                float h3 = fmaxf(d[nt][3] + p1.y + bb1, 0.f);
                int w0 = (wr + g) * 36 + nt * 4 + t;
                sH[w0]       = packh2(h0, h1);
                sH[w0 + 288] = packh2(h2, h3);
            }
        }
        __syncwarp();

        // ---- GEMM2: K=64 (fp16 2-pass) ----
        float d2[8][4];
        #pragma unroll
        for (int i = 0; i < 8; i++)
            #pragma unroll
            for (int j = 0; j < 4; j++) d2[i][j] = 0.0f;

        #pragma unroll 1
        for (int kt = 0; kt < 4; kt++) {
            uint32_t ah[4];
            ldsm_x4(ah, h0a + kt * 32u);
            uint32_t wHi = sbase + E_SW2_HI + bOff + kt * 32u;
            uint32_t wLo = sbase + E_SW2_LO + bOff + kt * 32u;
            #pragma unroll
            for (int p = 0; p < 4; p++) {
                uint32_t bh[4], bl[4];
                ldsm_x4(bh, wHi + p * 2304u);
                ldsm_x4(bl, wLo + p * 2304u);
                mma16816(d2[2 * p],     ah, bh);
                mma16816(d2[2 * p + 1], ah, bh + 2);
                mma16816(d2[2 * p],     ah, bl);
                mma16816(d2[2 * p + 1], ah, bl + 2);
            }
        }
        __syncwarp();   // Psum fully consumed by all lanes (epi1 done) before reuse

        // ---- epilogue 2: stage e rows into stg (warp-private), then
        //      coalesced STG.128 + 8-lane-per-line red.v2 ----
        {
            #pragma unroll
            for (int nt = 0; nt < 8; nt++) {
                int c0 = nt * 8 + 2 * t;
                float bb0 = bias2[c0], bb1 = bias2[c0 + 1];
                *(float2*)(stg + (wr + g) * 68 + c0) =
                    make_float2(d2[nt][0] + bb0, d2[nt][1] + bb1);
                *(float2*)(stg + (wr + 8 + g) * 68 + c0) =
                    make_float2(d2[nt][2] + bb0, d2[nt][3] + bb1);
            }
            __syncwarp();
            #pragma unroll
            for (int i = 0; i < 8; i++) {
                int rw = wr + 2 * i + g2;
                int er = ebase + rw;
                bool v = er < n_edges;
                int cn = sc[rw];
                float4 val = *(const float4*)(stg + rw * 68 + hf * 32 + c8);
                if (v) {
                    stg_cs4(e_out + (size_t)er * 64 + hf * 32 + c8, val);
                    float* ag = g_agg + (size_t)cn * 64 + hf * 32 + c8;
                    red_add2(ag, val.x, val.y);
                    red_add2(ag + 2, val.z, val.w);
                }
            }
        }
        __syncwarp();
    }
}

// ======================= node kernel =======================
#define N_SA      0u
#define N_SW1_HI  34816u
#define N_SW1_LO  52224u
#define N_SH      69632u
#define N_SW2_HI  88064u
#define N_SW2_LO  97280u
#define N_BIAS1   106496u
#define N_BIAS2   106752u
#define N_SMEM    107008u

__global__ void __launch_bounds__(256, 1) node_kernel(
    const float* __restrict__ feats,
    const float* __restrict__ W1n, const float* __restrict__ b1n,
    const float* __restrict__ W2n, const float* __restrict__ b2n,
    float* __restrict__ feats_out,
    int n_nodes)
{
    extern __shared__ char smem[];
    uint32_t* sA = (uint32_t*)(smem + N_SA);
    uint32_t* sH = (uint32_t*)(smem + N_SH);
    float* bias1 = (float*)(smem + N_BIAS1);
    float* bias2 = (float*)(smem + N_BIAS2);

    int tid = threadIdx.x;

    for (int i = tid; i < 128 * 64; i += 256) {
        int k = i >> 6, n = i & 63;
        float w = W1n[i];
        __half wh, wl;
        wsplit(w, wh, wl);
        ((__half*)(smem + N_SW1_HI))[n * 136 + k] = wh;
        ((__half*)(smem + N_SW1_LO))[n * 136 + k] = wl;
    }
    for (int i = tid; i < 64 * 64; i += 256) {
        int k = i >> 6, n = i & 63;
        float w = W2n[i];
        __half wh, wl;
        wsplit(w, wh, wl);
        ((__half*)(smem + N_SW2_HI))[n * 72 + k] = wh;
        ((__half*)(smem + N_SW2_LO))[n * 72 + k] = wl;
    }
    if (tid < 64) {
        bias1[tid] = b1n[tid];
        bias2[tid] = b2n[tid];
    }
    __syncthreads();

    const int warp = tid >> 5, lane = tid & 31;
    const int g = lane >> 2, t = lane & 3;
    const int wr = warp << 4;

    const int r8 = lane & 7;
    const int m01 = (lane >> 3) & 1;
    const int q01 = lane >> 4;
    uint32_t sbase = (uint32_t)__cvta_generic_to_shared(smem);
    uint32_t a0 = sbase + N_SA + ((uint32_t)(wr + r8 + m01 * 8) * 68u + q01 * 4u) * 4u;
    uint32_t fragRow36 = ((uint32_t)(wr + r8 + m01 * 8) * 36u + q01 * 4u) * 4u;
    uint32_t h0a = sbase + N_SH + fragRow36;
    uint32_t bOff68 = ((uint32_t)(q01 * 8 + r8) * 68u + m01 * 4u) * 4u;
    uint32_t bOff36 = ((uint32_t)(q01 * 8 + r8) * 36u + m01 * 4u) * 4u;

    int nTiles = (n_nodes + 127) >> 7;

    for (int tile = blockIdx.x; tile < nTiles; tile += gridDim.x) {
        int nbase = tile << 7;

        {
            float invdReg;
            {
                int r16 = nbase + wr + (lane & 15);
                int nid = r16 < n_nodes ? r16 : (n_nodes - 1);
                invdReg = 1.0f / fmaxf(g_deg[nid], 1.0f);
            }
            size_t base4 = (size_t)(nbase + wr) * 16;
            size_t max4 = (size_t)n_nodes * 16 - 1;
            #pragma unroll
            for (int j = 0; j < 8; j++) {
                int idx = j * 32 + lane;
                size_t gidx = base4 + idx; if (gidx > max4) gidx = max4;
                float4 va = ((const float4*)feats)[gidx];
                int rloc = wr + (idx >> 4);
                int c4 = idx & 15;
                *(uint2*)(sA + rloc * 68 + c4 * 2) =
                    make_uint2(packh2(va.x, va.y), packh2(va.z, va.w));
            }
            #pragma unroll
            for (int j = 0; j < 8; j++) {
                int idx = j * 32 + lane;
                size_t gidx = base4 + idx; if (gidx > max4) gidx = max4;
                float4 va = ((const float4*)g_agg)[gidx];
                float s = __shfl_sync(0xffffffffu, invdReg, idx >> 4);
                va.x *= s; va.y *= s; va.z *= s; va.w *= s;
                int rloc = wr + (idx >> 4);
                int c4 = idx & 15;
                *(uint2*)(sA + rloc * 68 + 32 + c4 * 2) =
                    make_uint2(packh2(va.x, va.y), packh2(va.z, va.w));
            }
        }
        __syncwarp();

        float d[8][4];
        #pragma unroll
        for (int i = 0; i < 8; i++)
            #pragma unroll
            for (int j = 0; j < 4; j++) d[i][j] = 0.0f;

        #pragma unroll 1
        for (int kt = 0; kt < 8; kt++) {
            uint32_t ah[4];
            ldsm_x4(ah, a0 + kt * 32u);
            uint32_t wHi = sbase + N_SW1_HI + bOff68 + kt * 32u;
            uint32_t wLo = sbase + N_SW1_LO + bOff68 + kt * 32u;
            #pragma unroll
            for (int p = 0; p < 4; p++) {
                uint32_t bh[4], bl[4];
                ldsm_x4(bh, wHi + p * 4352u);
                ldsm_x4(bl, wLo + p * 4352u);
                mma16816(d[2 * p],     ah, bh);
                mma16816(d[2 * p + 1], ah, bh + 2);
                mma16816(d[2 * p],     ah, bl);
                mma16816(d[2 * p + 1], ah, bl + 2);
            }
        }

        #pragma unroll
        for (int nt = 0; nt < 8; nt++) {
            int c0 = nt * 8 + 2 * t;
            float bb0 = bias1[c0], bb1 = bias1[c0 + 1];
            float h0 = fmaxf(d[nt][0] + bb0, 0.f), h1 = fmaxf(d[nt][1] + bb1, 0.f);
            float h2 = fmaxf(d[nt][2] + bb0, 0.f), h3 = fmaxf(d[nt][3] + bb1, 0.f);
            int w0 = (wr + g) * 36 + nt * 4 + t;
            sH[w0]       = packh2(h0, h1);
            sH[w0 + 288] = packh2(h2, h3);
        }
        __syncwarp();

        float d2[8][4];
        #pragma unroll
        for (int i = 0; i < 8; i++)
            #pragma unroll
            for (int j = 0; j < 4; j++) d2[i][j] = 0.0f;

        #pragma unroll 1
        for (int kt = 0; kt < 4; kt++) {
            uint32_t ah[4];
            ldsm_x4(ah, h0a + kt * 32u);
            uint32_t wHi = sbase + N_SW2_HI + bOff36 + kt * 32u;
            uint32_t wLo = sbase + N_SW2_LO + bOff36 + kt * 32u;
            #pragma unroll
            for (int p = 0; p < 4; p++) {
                uint32_t bh[4], bl[4];
                ldsm_x4(bh, wHi + p * 2304u);
                ldsm_x4(bl, wLo + p * 2304u);
                mma16816(d2[2 * p],     ah, bh);
                mma16816(d2[2 * p + 1], ah, bh + 2);
                mma16816(d2[2 * p],     ah, bl);
                mma16816(d2[2 * p + 1], ah, bl + 2);
            }
        }

        {
            int r0 = nbase + wr + g, r1 = r0 + 8;
            bool v0 = r0 < n_nodes, v1 = r1 < n_nodes;
            #pragma unroll
            for (int nt = 0; nt < 8; nt++) {
                int c0 = nt * 8 + 2 * t;
                float bb0 = bias2[c0], bb1 = bias2[c0 + 1];
                if (v0)
                    stg_cs2(feats_out + (size_t)r0 * 64 + c0,
                            d2[nt][0] + bb0, d2[nt][1] + bb1);
                if (v1)
                    stg_cs2(feats_out + (size_t)r1 * 64 + c0,
                            d2[nt][2] + bb0, d2[nt][3] + bb1);
            }
        }
        __syncwarp();
    }
}

// ======================= launch =======================
extern "C" void kernel_launch(void* const* d_in, const int* in_sizes, int n_in,
                              void* d_out, int out_size) {
    const float* feats      = (const float*)d_in[0];
    const int*   edge_index = (const int*)d_in[1];
    const float* edge_attr  = (const float*)d_in[2];
    const float* W1e        = (const float*)d_in[3];
    const float* b1e        = (const float*)d_in[4];
    const float* W2e        = (const float*)d_in[5];
    const float* b2e        = (const float*)d_in[6];
    const float* W1n        = (const float*)d_in[7];
    const float* b1n        = (const float*)d_in[8];
    const float* W2n        = (const float*)d_in[9];
    const float* b2n        = (const float*)d_in[10];

    int n_nodes = in_sizes[0] / 64;
    int n_edges = in_sizes[2] / 64;

    float* out       = (float*)d_out;
    float* feats_out = out;                          // [n_nodes, 64]
    float* e_out     = out + (size_t)n_nodes * 64;   // [n_edges, 64]

    cudaFuncSetAttribute(pnode_kernel, cudaFuncAttributeMaxDynamicSharedMemorySize, P_SMEM);
    cudaFuncSetAttribute(edge_kernel, cudaFuncAttributeMaxDynamicSharedMemorySize, E_SMEM);
    cudaFuncSetAttribute(node_kernel, cudaFuncAttributeMaxDynamicSharedMemorySize, N_SMEM);

    zero_kernel<<<1024, 256>>>(n_nodes);
    pnode_kernel<<<296, 256, P_SMEM>>>(feats, W1e, n_nodes);
    edge_kernel<<<296, 256, E_SMEM>>>(feats, edge_index, edge_attr,
                                      W1e, b1e, W2e, b2e, e_out, n_edges);
    node_kernel<<<148, 256, N_SMEM>>>(feats, W1n, b1n, W2n, b2n,
                                      feats_out, n_nodes);
}